// round 4
// baseline (speedup 1.0000x reference)
#include <cuda_runtime.h>
#include <cuda_bf16.h>
#include <math.h>

// Problem constants
#define Bq    1
#define CIN   256
#define COUT  128
#define Hh    64
#define Ww    192
#define HW    (Hh*Ww)          // 12288
#define Hp    (Hh+2)           // 66
#define Wp    (Ww+2)           // 194
#define Pp    (Hp*Wp)          // 12804
#define TAPS  36               // 9 taps x 4 gathers
#define EPSv  1e-5f
#define LEAK  0.01f

// ---------------- scratch (static __device__ — no allocation) ----------------
__device__ int   g_tidx[TAPS * HW];      // gather indices into UNPADDED x, tap-major
__device__ float g_tw[TAPS * HW];        // gather weights (0 where tap hits pad ring)
__device__ float g_y0[CIN * HW];         // deformable-gather output (12.6 MB)
__device__ float g_t1[COUT * HW];
__device__ float g_t2[COUT * HW];
__device__ float g_t3[COUT * HW];
__device__ float g_sum[3][COUT];         // per-stage channel sums
__device__ float g_sum2[3][COUT];        // per-stage channel sum-of-squares

// ---------------- 0) zero the stat accumulators ----------------
__global__ void init_kernel() {
    int i = threadIdx.x;
    if (i < COUT) {
        #pragma unroll
        for (int s = 0; s < 3; s++) { g_sum[s][i] = 0.f; g_sum2[s][i] = 0.f; }
    }
}

// ---------------- 1) per-pixel gather tables ----------------
__device__ __forceinline__ void emit_tap(int slot, int p, float av_padded, float w) {
    int id = (int)av_padded;          // 0 .. Pp-1
    int r  = id / Wp;
    int cc = id - r * Wp;
    int idx = 0;
    if (r >= 1 && r <= Hh && cc >= 1 && cc <= Ww)
        idx = (r - 1) * Ww + (cc - 1);
    else
        w = 0.f;
    g_tidx[slot * HW + p] = idx;
    g_tw[slot * HW + p]   = w;
}

__global__ void tab_kernel(const float* __restrict__ xr) {
    int p = blockIdx.x * 256 + threadIdx.x;
    if (p >= HW) return;
    float off = 3.0f * (1.0f / (1.0f + expf(-xr[p])));
    int r = p / Ww, cc = p - r * Ww;
    float v0 = (float)((r + 1) * Wp + (cc + 1));
    const float xo9[9] = {-1,0,1,-1,0,1,-1,0,1};
    const float yo9[9] = {-1,-1,-1,0,0,0,1,1,1};
    const float Pm1 = (float)(Pp - 1);
    const float Wpf = (float)Wp;
    #pragma unroll
    for (int k = 0; k < 9; k++) {
        float xo = xo9[k], yo = yo9[k];
        float pre  = v0 + xo + yo * Wpf;                       // exact ints in fp32
        float offv = __fadd_rn(__fmul_rn(off, xo), yo * Wpf);  // match mul-then-add
        float after = __fadd_rn(pre, offv);
        float avf  = fminf(fmaxf(pre + floorf(offv), 0.f), Pm1);
        float avf1 = fminf(fmaxf(avf + xo, 0.f), Pm1);
        float avc  = fminf(fmaxf(pre + ceilf(offv), 0.f), Pm1);
        float avc1 = fminf(fmaxf(avc + xo, 0.f), Pm1);
        float g1w = fabsf((after - avf)  / Wpf);
        float g2w = fabsf((avc1 - after) / Wpf);
        float wf  = fabsf(after - avf);
        float wf1 = fabsf(avf1 - after);
        float wc1 = fabsf(after - avc1);
        float wc  = fabsf(avc  - after);
        int t = k * 4;
        emit_tap(t + 0, p, avf,  g1w * wf);
        emit_tap(t + 1, p, avf1, g1w * wf1);
        emit_tap(t + 2, p, avc1, g2w * wc1);
        emit_tap(t + 3, p, avc,  g2w * wc);
    }
}

// ---------------- 2) deformable gather-contraction ----------------
__global__ void gather_kernel(const float* __restrict__ x,
                              const float* __restrict__ ro /* (CIN,9) */) {
    __shared__ int   s_idx[TAPS * 64];
    __shared__ float s_w[TAPS * 64];
    __shared__ float s_ro[64 * 9];
    int p0 = blockIdx.x * 64;
    int c0 = blockIdx.y * 64;
    int tid = threadIdx.x;
    for (int i = tid; i < TAPS * 64; i += 256) {
        int t = i >> 6, px = i & 63;
        s_idx[i] = g_tidx[t * HW + p0 + px];
        s_w[i]   = g_tw[t * HW + p0 + px];
    }
    for (int i = tid; i < 64 * 9; i += 256) {
        int cl = i / 9, k = i - cl * 9;
        s_ro[i] = ro[(c0 + cl) * 9 + k];
    }
    __syncthreads();
    int px = tid & 63;
    int cg = tid >> 6;
    int p = p0 + px;
    #pragma unroll 1
    for (int ci = 0; ci < 16; ci++) {
        int cl = cg * 16 + ci;
        int c  = c0 + cl;
        const float* xp = x + (size_t)c * HW;
        float acc = 0.f;
        #pragma unroll
        for (int k = 0; k < 9; k++) {
            float rk = s_ro[cl * 9 + k];
            #pragma unroll
            for (int j = 0; j < 4; j++) {
                int t = k * 4 + j;
                int id = s_idx[t * 64 + px];
                float wv = s_w[t * 64 + px];
                acc = fmaf(wv * rk, __ldg(xp + id), acc);
            }
        }
        g_y0[(size_t)c * HW + p] = acc;
    }
}

// ---------------- 3) fp32 GEMM + fused BN-stat epilogue ----------------
// C[128,N] = A[128,K] * B[K,N]; BM=128 (all M), BN=64, BK=16, 256 threads,
// 8x4 microtile. Epilogue: per-channel sum/sumsq atomics.
__global__ void __launch_bounds__(256, 2)
gemm_kernel(const float* __restrict__ A, const float* __restrict__ B,
            float* __restrict__ C, int K,
            float* __restrict__ sum, float* __restrict__ sum2) {
    __shared__ float As[16][132];   // 132 floats = 528B row stride, 16B aligned
    __shared__ float Bs[16][64];
    const int N = HW;
    int bn = blockIdx.x * 64;
    int tid = threadIdx.x;
    int tx = tid & 15, ty = tid >> 4;
    int am = tid >> 1;              // A row, 0..127
    int ak = (tid & 1) * 8;         // A k-offset, 0 or 8
    int bk = tid >> 4;              // B k row 0..15
    int bnn = (tid & 15) * 4;       // B col group
    float acc[8][4] = {};
    for (int k0 = 0; k0 < K; k0 += 16) {
        float4 a0 = *(const float4*)&A[(size_t)am * K + k0 + ak];
        float4 a1 = *(const float4*)&A[(size_t)am * K + k0 + ak + 4];
        float4 bv = *(const float4*)&B[(size_t)(k0 + bk) * N + bn + bnn];
        As[ak + 0][am] = a0.x; As[ak + 1][am] = a0.y;
        As[ak + 2][am] = a0.z; As[ak + 3][am] = a0.w;
        As[ak + 4][am] = a1.x; As[ak + 5][am] = a1.y;
        As[ak + 6][am] = a1.z; As[ak + 7][am] = a1.w;
        *(float4*)&Bs[bk][bnn] = bv;
        __syncthreads();
        #pragma unroll
        for (int k = 0; k < 16; k++) {
            float4 A0 = *(const float4*)&As[k][ty * 8];
            float4 A1 = *(const float4*)&As[k][ty * 8 + 4];
            float4 b4 = *(const float4*)&Bs[k][tx * 4];
            float a[8] = {A0.x, A0.y, A0.z, A0.w, A1.x, A1.y, A1.z, A1.w};
            float b[4] = {b4.x, b4.y, b4.z, b4.w};
            #pragma unroll
            for (int i = 0; i < 8; i++)
                #pragma unroll
                for (int j = 0; j < 4; j++)
                    acc[i][j] = fmaf(a[i], b[j], acc[i][j]);
        }
        __syncthreads();
    }
    #pragma unroll
    for (int i = 0; i < 8; i++) {
        int m = ty * 8 + i;
        float4 v = make_float4(acc[i][0], acc[i][1], acc[i][2], acc[i][3]);
        *(float4*)&C[(size_t)m * N + bn + tx * 4] = v;
        float s  = acc[i][0] + acc[i][1] + acc[i][2] + acc[i][3];
        float s2 = fmaf(acc[i][0], acc[i][0],
                   fmaf(acc[i][1], acc[i][1],
                   fmaf(acc[i][2], acc[i][2], acc[i][3] * acc[i][3])));
        #pragma unroll
        for (int off = 8; off > 0; off >>= 1) {
            s  += __shfl_down_sync(0xffffffffu, s,  off, 16);
            s2 += __shfl_down_sync(0xffffffffu, s2, off, 16);
        }
        if (tx == 0) {
            atomicAdd(&sum[m],  s);
            atomicAdd(&sum2[m], s2);
        }
    }
}

// ---------------- BN scale/bias from accumulated stats ----------------
__device__ __forceinline__ void bn_coeffs(int c, const float* sum, const float* sum2,
                                          const float* __restrict__ g,
                                          const float* __restrict__ b,
                                          float& sc, float& bi) {
    float mean = sum[c] * (1.f / (float)HW);
    float var  = sum2[c] * (1.f / (float)HW) - mean * mean;
    float rstd = rsqrtf(var + EPSv);
    sc = g[c] * rstd;
    bi = b[c] - mean * sc;
}

__device__ __forceinline__ float bn_leaky(float v, float sc, float bi) {
    float y = fmaf(v, sc, bi);
    return y >= 0.f ? y : LEAK * y;
}

// ---------------- 4) depthwise 3x3 with fused BN+leaky on input ----------------
__global__ void dw_kernel(const float* __restrict__ in, const float* __restrict__ dw,
                          float* __restrict__ out,
                          const float* __restrict__ sum, const float* __restrict__ sum2,
                          const float* __restrict__ g, const float* __restrict__ b) {
    int c = blockIdx.y;
    int p = blockIdx.x * 256 + threadIdx.x;
    if (p >= HW) return;
    int r = p / Ww, col = p - r * Ww;
    float sc, bi;
    bn_coeffs(c, sum, sum2, g, b, sc, bi);
    float wl[9];
    #pragma unroll
    for (int i = 0; i < 9; i++) wl[i] = dw[c * 9 + i];
    const float* ip = in + (size_t)c * HW;
    float acc = 0.f;
    #pragma unroll
    for (int dy = -1; dy <= 1; dy++) {
        int rr = r + dy;
        if (rr < 0 || rr >= Hh) continue;
        #pragma unroll
        for (int dx = -1; dx <= 1; dx++) {
            int cc = col + dx;
            if (cc < 0 || cc >= Ww) continue;
            float v = bn_leaky(ip[rr * Ww + cc], sc, bi);
            acc = fmaf(v, wl[(dy + 1) * 3 + (dx + 1)], acc);
        }
    }
    out[(size_t)c * HW + p] = acc;
}

// ---------------- 5) final BN+leaky apply (vectorized) ----------------
__global__ void apply_kernel(const float* __restrict__ in, float* __restrict__ out,
                             const float* __restrict__ sum, const float* __restrict__ sum2,
                             const float* __restrict__ g, const float* __restrict__ b) {
    int i = blockIdx.x * 256 + threadIdx.x;       // float4 index
    if (i >= COUT * HW / 4) return;
    int c = (i * 4) / HW;                          // HW % 4 == 0 -> uniform in vec
    float sc, bi;
    bn_coeffs(c, sum, sum2, g, b, sc, bi);
    float4 v = ((const float4*)in)[i];
    v.x = bn_leaky(v.x, sc, bi);
    v.y = bn_leaky(v.y, sc, bi);
    v.z = bn_leaky(v.z, sc, bi);
    v.w = bn_leaky(v.w, sc, bi);
    ((float4*)out)[i] = v;
}

// ---------------- launch ----------------
extern "C" void kernel_launch(void* const* d_in, const int* in_sizes, int n_in,
                              void* d_out, int out_size) {
    const float* x        = (const float*)d_in[0];
    const float* x_range  = (const float*)d_in[1];
    const float* range_o  = (const float*)d_in[2];
    const float* w_reduce = (const float*)d_in[3];
    const float* g_r      = (const float*)d_in[4];
    const float* b_r      = (const float*)d_in[5];
    const float* dw1      = (const float*)d_in[6];
    const float* pw1      = (const float*)d_in[7];
    const float* g1       = (const float*)d_in[8];
    const float* b1       = (const float*)d_in[9];
    const float* dw2      = (const float*)d_in[10];
    const float* pw2      = (const float*)d_in[11];
    const float* g2       = (const float*)d_in[12];
    const float* b2       = (const float*)d_in[13];
    float* out = (float*)d_out;

    float *t1, *t2, *t3, *y0, *sumb, *sum2b;
    cudaGetSymbolAddress((void**)&t1, g_t1);
    cudaGetSymbolAddress((void**)&t2, g_t2);
    cudaGetSymbolAddress((void**)&t3, g_t3);
    cudaGetSymbolAddress((void**)&y0, g_y0);
    cudaGetSymbolAddress((void**)&sumb, g_sum);
    cudaGetSymbolAddress((void**)&sum2b, g_sum2);
    float* s0  = sumb;            float* q0 = sum2b;
    float* s1  = sumb + COUT;     float* q1 = sum2b + COUT;
    float* s2  = sumb + 2*COUT;   float* q2 = sum2b + 2*COUT;

    init_kernel<<<1, 128>>>();
    tab_kernel<<<(HW + 255) / 256, 256>>>(x_range);
    gather_kernel<<<dim3(HW / 64, CIN / 64), 256>>>(x, range_o);

    gemm_kernel<<<HW / 64, 256>>>(w_reduce, y0, t1, CIN, s0, q0);
    dw_kernel<<<dim3((HW + 255) / 256, COUT), 256>>>(t1, dw1, t2, s0, q0, g_r, b_r);

    gemm_kernel<<<HW / 64, 256>>>(pw1, t2, t3, COUT, s1, q1);
    dw_kernel<<<dim3((HW + 255) / 256, COUT), 256>>>(t3, dw2, t2, s1, q1, g1, b1);

    gemm_kernel<<<HW / 64, 256>>>(pw2, t2, t1, COUT, s2, q2);
    apply_kernel<<<(COUT * HW / 4 + 255) / 256, 256>>>(t1, out, s2, q2, g2, b2);
}

// round 5
// speedup vs baseline: 1.2656x; 1.2656x over previous
#include <cuda_runtime.h>
#include <cuda_bf16.h>
#include <math.h>

// Problem constants
#define Bq    1
#define CIN   256
#define COUT  128
#define Hh    64
#define Ww    192
#define HW    (Hh*Ww)          // 12288
#define Hp    (Hh+2)           // 66
#define Wp    (Ww+2)           // 194
#define Pp    (Hp*Wp)          // 12804
#define EPSv  1e-5f
#define LEAK  0.01f

// ---------------- scratch (static __device__ — no allocation) ----------------
__device__ int   g_tbase[9 * HW];        // per-tap window base index into UNPADDED x
__device__ float g_tw3[27 * HW];         // per-tap 3 positional weights
__device__ float g_y0[CIN * HW];         // deformable-gather output (12.6 MB)
__device__ float g_t1[COUT * HW];
__device__ float g_t2[COUT * HW];
__device__ float g_t3[COUT * HW];
__device__ float g_sum[3][COUT];         // per-stage channel sums
__device__ float g_sum2[3][COUT];        // per-stage channel sum-of-squares

// ---------------- 0) zero the stat accumulators ----------------
__global__ void init_kernel() {
    int i = threadIdx.x;
    if (i < COUT) {
        #pragma unroll
        for (int s = 0; s < 3; s++) { g_sum[s][i] = 0.f; g_sum2[s][i] = 0.f; }
    }
}

// ---------------- 1) per-pixel gather tables (window-compressed) ----------------
// Per tap, the 4 bilinear sample indices {avf, avf+xo, avc, avc+xo} lie in a
// width-3 consecutive window of flat PADDED indices. We merge the 4 weights
// into 3 positional weights, zero slots on the pad ring (value there is 0),
// and store one UNPADDED base index + 3 weights. Valid slots are consecutive
// in unpadded space (pads occur only as contiguous runs at row boundaries).
__global__ void tab_kernel(const float* __restrict__ xr) {
    int p = blockIdx.x * 256 + threadIdx.x;
    if (p >= HW) return;
    float off = 3.0f * (1.0f / (1.0f + expf(-xr[p])));
    int r = p / Ww, cc = p - r * Ww;
    float v0 = (float)((r + 1) * Wp + (cc + 1));
    const float xo9[9] = {-1,0,1,-1,0,1,-1,0,1};
    const float yo9[9] = {-1,-1,-1,0,0,0,1,1,1};
    const float Pm1 = (float)(Pp - 1);
    const float Wpf = (float)Wp;
    #pragma unroll
    for (int k = 0; k < 9; k++) {
        float xo = xo9[k], yo = yo9[k];
        float pre  = v0 + xo + yo * Wpf;                       // exact ints in fp32
        float offv = __fadd_rn(__fmul_rn(off, xo), yo * Wpf);  // match mul-then-add
        float after = __fadd_rn(pre, offv);
        float avf  = fminf(fmaxf(pre + floorf(offv), 0.f), Pm1);
        float avf1 = fminf(fmaxf(avf + xo, 0.f), Pm1);
        float avc  = fminf(fmaxf(pre + ceilf(offv), 0.f), Pm1);
        float avc1 = fminf(fmaxf(avc + xo, 0.f), Pm1);
        float g1w = fabsf((after - avf)  / Wpf);
        float g2w = fabsf((avc1 - after) / Wpf);
        float wq[4];
        wq[0] = g1w * fabsf(after - avf);
        wq[1] = g1w * fabsf(avf1 - after);
        wq[2] = g2w * fabsf(after - avc1);
        wq[3] = g2w * fabsf(avc  - after);
        int iq[4] = {(int)avf, (int)avf1, (int)avc1, (int)avc};
        int lo = min(min(iq[0], iq[1]), min(iq[2], iq[3]));
        float w3[3] = {0.f, 0.f, 0.f};
        #pragma unroll
        for (int j = 0; j < 4; j++) w3[iq[j] - lo] += wq[j];
        // zero pad-ring slots; find first valid nonzero slot
        int vbase = -1, firstslot = 0;
        #pragma unroll
        for (int s = 0; s < 3; s++) {
            int id = lo + s;                       // may exceed hi; weight 0 there
            int rr = id / Wp, c2 = id - rr * Wp;
            bool valid = (rr >= 1 && rr <= Hh && c2 >= 1 && c2 <= Ww);
            if (!valid) w3[s] = 0.f;
            else if (w3[s] != 0.f && vbase < 0) {
                vbase = (rr - 1) * Ww + (c2 - 1);
                firstslot = s;
            }
        }
        float fw[3] = {0.f, 0.f, 0.f};
        int bidx = 0;
        if (vbase >= 0) {
            int base = vbase - firstslot;          // unpadded index of slot 0
            bidx = min(max(base, 0), HW - 3);
            #pragma unroll
            for (int s = 0; s < 3; s++)
                if (w3[s] != 0.f) fw[(base + s) - bidx] += w3[s];
        }
        g_tbase[k * HW + p] = bidx;
        g_tw3[(k * 3 + 0) * HW + p] = fw[0];
        g_tw3[(k * 3 + 1) * HW + p] = fw[1];
        g_tw3[(k * 3 + 2) * HW + p] = fw[2];
    }
}

// ---------------- 2) deformable gather-contraction ----------------
// block: 64 pixels x 64 channels, 256 threads (64 px x 4 channel groups)
__global__ void gather_kernel(const float* __restrict__ x,
                              const float* __restrict__ ro /* (CIN,9) */) {
    __shared__ int   s_base[9 * 64];
    __shared__ float s_w[27 * 64];
    __shared__ float s_ro[64 * 9];
    int p0 = blockIdx.x * 64;
    int c0 = blockIdx.y * 64;
    int tid = threadIdx.x;
    for (int i = tid; i < 9 * 64; i += 256) {
        int t = i >> 6, px = i & 63;
        s_base[i] = g_tbase[t * HW + p0 + px];
    }
    for (int i = tid; i < 27 * 64; i += 256) {
        int t = i >> 6, px = i & 63;
        s_w[i] = g_tw3[t * HW + p0 + px];
    }
    for (int i = tid; i < 64 * 9; i += 256) {
        int cl = i / 9, k = i - cl * 9;
        s_ro[i] = ro[(c0 + cl) * 9 + k];
    }
    __syncthreads();
    int px = tid & 63;
    int cg = tid >> 6;
    int p = p0 + px;
    #pragma unroll 1
    for (int ci = 0; ci < 16; ci++) {
        int cl = cg * 16 + ci;
        int c  = c0 + cl;
        const float* xp = x + (size_t)c * HW;
        float acc = 0.f;
        #pragma unroll
        for (int k = 0; k < 9; k++) {
            float rk = s_ro[cl * 9 + k];
            int   b  = s_base[k * 64 + px];
            float w0 = s_w[(k * 3 + 0) * 64 + px];
            float w1 = s_w[(k * 3 + 1) * 64 + px];
            float w2 = s_w[(k * 3 + 2) * 64 + px];
            const float* xb = xp + b;
            float s = fmaf(w0, __ldg(xb + 0),
                      fmaf(w1, __ldg(xb + 1),
                           w2 * __ldg(xb + 2)));
            acc = fmaf(rk, s, acc);
        }
        g_y0[(size_t)c * HW + p] = acc;
    }
}

// ---------------- 3) fp32 GEMM + fused BN-stat epilogue ----------------
// C[128,N] = A[128,K] * B[K,N]; 64x64 tile, BK=16, 256 threads, 4x4 microtile,
// software-prefetched global loads. Epilogue: per-channel sum/sumsq atomics.
__global__ void gemm_kernel(const float* __restrict__ A, const float* __restrict__ B,
                            float* __restrict__ C, int K,
                            float* __restrict__ sum, float* __restrict__ sum2) {
    __shared__ float As[16][68];    // 68: keeps As[k][4*ty] 16B-aligned
    __shared__ float Bs[16][64];
    const int N = HW;
    int bn = blockIdx.x * 64, bm = blockIdx.y * 64;
    int tid = threadIdx.x;
    int tx = tid & 15, ty = tid >> 4;
    int am  = tid >> 2;             // A row within tile
    int akk = (tid & 3) * 4;        // A k-offset
    int bk  = tid >> 4;             // B k row
    int bnn = (tid & 15) * 4;       // B col group
    const float* Ap = &A[(size_t)(bm + am) * K + akk];
    const float* Bp = &B[(size_t)bk * N + bn + bnn];
    float4 av = *(const float4*)Ap;
    float4 bv = *(const float4*)Bp;
    float acc[4][4] = {};
    for (int k0 = 0; k0 < K; k0 += 16) {
        As[akk + 0][am] = av.x; As[akk + 1][am] = av.y;
        As[akk + 2][am] = av.z; As[akk + 3][am] = av.w;
        *(float4*)&Bs[bk][bnn] = bv;
        __syncthreads();
        if (k0 + 16 < K) {                       // prefetch next stage
            av = *(const float4*)(Ap + k0 + 16);
            bv = *(const float4*)(Bp + (size_t)(k0 + 16) * N);
        }
        #pragma unroll
        for (int k = 0; k < 16; k++) {
            float4 a4 = *(const float4*)&As[k][ty * 4];
            float4 b4 = *(const float4*)&Bs[k][tx * 4];
            float a[4] = {a4.x, a4.y, a4.z, a4.w};
            float b[4] = {b4.x, b4.y, b4.z, b4.w};
            #pragma unroll
            for (int i = 0; i < 4; i++)
                #pragma unroll
                for (int j = 0; j < 4; j++)
                    acc[i][j] = fmaf(a[i], b[j], acc[i][j]);
        }
        __syncthreads();
    }
    #pragma unroll
    for (int i = 0; i < 4; i++) {
        int m = bm + ty * 4 + i;
        float4 v = make_float4(acc[i][0], acc[i][1], acc[i][2], acc[i][3]);
        *(float4*)&C[(size_t)m * N + bn + tx * 4] = v;
        float s  = acc[i][0] + acc[i][1] + acc[i][2] + acc[i][3];
        float s2 = fmaf(acc[i][0], acc[i][0],
                   fmaf(acc[i][1], acc[i][1],
                   fmaf(acc[i][2], acc[i][2], acc[i][3] * acc[i][3])));
        #pragma unroll
        for (int off = 8; off > 0; off >>= 1) {
            s  += __shfl_down_sync(0xffffffffu, s,  off, 16);
            s2 += __shfl_down_sync(0xffffffffu, s2, off, 16);
        }
        if (tx == 0) {
            atomicAdd(&sum[m],  s);
            atomicAdd(&sum2[m], s2);
        }
    }
}

// ---------------- BN scale/bias from accumulated stats ----------------
__device__ __forceinline__ void bn_coeffs(int c, const float* sum, const float* sum2,
                                          const float* __restrict__ g,
                                          const float* __restrict__ b,
                                          float& sc, float& bi) {
    float mean = sum[c] * (1.f / (float)HW);
    float var  = sum2[c] * (1.f / (float)HW) - mean * mean;
    float rstd = rsqrtf(var + EPSv);
    sc = g[c] * rstd;
    bi = b[c] - mean * sc;
}

__device__ __forceinline__ float bn_leaky(float v, float sc, float bi) {
    float y = fmaf(v, sc, bi);
    return y >= 0.f ? y : LEAK * y;
}

// ---------------- 4) depthwise 3x3 with fused BN+leaky on input ----------------
__global__ void dw_kernel(const float* __restrict__ in, const float* __restrict__ dw,
                          float* __restrict__ out,
                          const float* __restrict__ sum, const float* __restrict__ sum2,
                          const float* __restrict__ g, const float* __restrict__ b) {
    int c = blockIdx.y;
    int p = blockIdx.x * 256 + threadIdx.x;
    if (p >= HW) return;
    int r = p / Ww, col = p - r * Ww;
    float sc, bi;
    bn_coeffs(c, sum, sum2, g, b, sc, bi);
    float wl[9];
    #pragma unroll
    for (int i = 0; i < 9; i++) wl[i] = dw[c * 9 + i];
    const float* ip = in + (size_t)c * HW;
    float acc = 0.f;
    #pragma unroll
    for (int dy = -1; dy <= 1; dy++) {
        int rr = r + dy;
        if (rr < 0 || rr >= Hh) continue;
        #pragma unroll
        for (int dx = -1; dx <= 1; dx++) {
            int cc = col + dx;
            if (cc < 0 || cc >= Ww) continue;
            float v = bn_leaky(ip[rr * Ww + cc], sc, bi);
            acc = fmaf(v, wl[(dy + 1) * 3 + (dx + 1)], acc);
        }
    }
    out[(size_t)c * HW + p] = acc;
}

// ---------------- 5) final BN+leaky apply (vectorized) ----------------
__global__ void apply_kernel(const float* __restrict__ in, float* __restrict__ out,
                             const float* __restrict__ sum, const float* __restrict__ sum2,
                             const float* __restrict__ g, const float* __restrict__ b) {
    int i = blockIdx.x * 256 + threadIdx.x;       // float4 index
    if (i >= COUT * HW / 4) return;
    int c = (i * 4) / HW;                          // HW % 4 == 0 -> uniform in vec
    float sc, bi;
    bn_coeffs(c, sum, sum2, g, b, sc, bi);
    float4 v = ((const float4*)in)[i];
    v.x = bn_leaky(v.x, sc, bi);
    v.y = bn_leaky(v.y, sc, bi);
    v.z = bn_leaky(v.z, sc, bi);
    v.w = bn_leaky(v.w, sc, bi);
    ((float4*)out)[i] = v;
}

// ---------------- launch ----------------
extern "C" void kernel_launch(void* const* d_in, const int* in_sizes, int n_in,
                              void* d_out, int out_size) {
    const float* x        = (const float*)d_in[0];
    const float* x_range  = (const float*)d_in[1];
    const float* range_o  = (const float*)d_in[2];
    const float* w_reduce = (const float*)d_in[3];
    const float* g_r      = (const float*)d_in[4];
    const float* b_r      = (const float*)d_in[5];
    const float* dw1      = (const float*)d_in[6];
    const float* pw1      = (const float*)d_in[7];
    const float* g1       = (const float*)d_in[8];
    const float* b1       = (const float*)d_in[9];
    const float* dw2      = (const float*)d_in[10];
    const float* pw2      = (const float*)d_in[11];
    const float* g2       = (const float*)d_in[12];
    const float* b2       = (const float*)d_in[13];
    float* out = (float*)d_out;

    float *t1, *t2, *t3, *y0, *sumb, *sum2b;
    cudaGetSymbolAddress((void**)&t1, g_t1);
    cudaGetSymbolAddress((void**)&t2, g_t2);
    cudaGetSymbolAddress((void**)&t3, g_t3);
    cudaGetSymbolAddress((void**)&y0, g_y0);
    cudaGetSymbolAddress((void**)&sumb, g_sum);
    cudaGetSymbolAddress((void**)&sum2b, g_sum2);
    float* s0  = sumb;            float* q0 = sum2b;
    float* s1  = sumb + COUT;     float* q1 = sum2b + COUT;
    float* s2  = sumb + 2*COUT;   float* q2 = sum2b + 2*COUT;

    init_kernel<<<1, 128>>>();
    tab_kernel<<<(HW + 255) / 256, 256>>>(x_range);
    gather_kernel<<<dim3(HW / 64, CIN / 64), 256>>>(x, range_o);

    gemm_kernel<<<dim3(HW / 64, COUT / 64), 256>>>(w_reduce, y0, t1, CIN, s0, q0);
    dw_kernel<<<dim3((HW + 255) / 256, COUT), 256>>>(t1, dw1, t2, s0, q0, g_r, b_r);

    gemm_kernel<<<dim3(HW / 64, COUT / 64), 256>>>(pw1, t2, t3, COUT, s1, q1);
    dw_kernel<<<dim3((HW + 255) / 256, COUT), 256>>>(t3, dw2, t2, s1, q1, g1, b1);

    gemm_kernel<<<dim3(HW / 64, COUT / 64), 256>>>(pw2, t2, t1, COUT, s2, q2);
    apply_kernel<<<(COUT * HW / 4 + 255) / 256, 256>>>(t1, out, s2, q2, g2, b2);
}

// round 6
// speedup vs baseline: 1.2697x; 1.0032x over previous
#include <cuda_runtime.h>
#include <cuda_bf16.h>
#include <math.h>

// Problem constants
#define Bq    1
#define CIN   256
#define COUT  128
#define Hh    64
#define Ww    192
#define HW    (Hh*Ww)          // 12288
#define Hp    (Hh+2)           // 66
#define Wp    (Ww+2)           // 194
#define Pp    (Hp*Wp)          // 12804
#define EPSv  1e-5f
#define LEAK  0.01f

// ---------------- scratch (static __device__ — no allocation) ----------------
__device__ int   g_tbase[9 * HW];        // per-tap window base index into UNPADDED x
__device__ float g_tw3[27 * HW];         // per-tap 3 positional weights
__device__ float g_y0[CIN * HW];         // deformable-gather output (12.6 MB)
__device__ float g_t1[COUT * HW];
__device__ float g_t2[COUT * HW];
__device__ float g_t3[COUT * HW];
__device__ float g_sum[3][COUT];         // per-stage channel sums
__device__ float g_sum2[3][COUT];        // per-stage channel sum-of-squares

// ---- packed fp32x2 helpers (Blackwell FFMA2) ----
#define FFMA2(d, a, b) \
    asm("fma.rn.f32x2 %0, %1, %2, %0;" : "+l"(d) : "l"(a), "l"(b))
#define PACKDUP(d, x) \
    asm("mov.b64 %0, {%1, %1};" : "=l"(d) : "r"(__float_as_uint(x)))

// ---------------- 0) zero the stat accumulators ----------------
__global__ void init_kernel() {
    int i = threadIdx.x;
    if (i < COUT) {
        #pragma unroll
        for (int s = 0; s < 3; s++) { g_sum[s][i] = 0.f; g_sum2[s][i] = 0.f; }
    }
}

// ---------------- 1) per-pixel gather tables (window-compressed) ----------------
__global__ void tab_kernel(const float* __restrict__ xr) {
    int p = blockIdx.x * 256 + threadIdx.x;
    if (p >= HW) return;
    float off = 3.0f * (1.0f / (1.0f + expf(-xr[p])));
    int r = p / Ww, cc = p - r * Ww;
    float v0 = (float)((r + 1) * Wp + (cc + 1));
    const float xo9[9] = {-1,0,1,-1,0,1,-1,0,1};
    const float yo9[9] = {-1,-1,-1,0,0,0,1,1,1};
    const float Pm1 = (float)(Pp - 1);
    const float Wpf = (float)Wp;
    #pragma unroll
    for (int k = 0; k < 9; k++) {
        float xo = xo9[k], yo = yo9[k];
        float pre  = v0 + xo + yo * Wpf;                       // exact ints in fp32
        float offv = __fadd_rn(__fmul_rn(off, xo), yo * Wpf);  // match mul-then-add
        float after = __fadd_rn(pre, offv);
        float avf  = fminf(fmaxf(pre + floorf(offv), 0.f), Pm1);
        float avf1 = fminf(fmaxf(avf + xo, 0.f), Pm1);
        float avc  = fminf(fmaxf(pre + ceilf(offv), 0.f), Pm1);
        float avc1 = fminf(fmaxf(avc + xo, 0.f), Pm1);
        float g1w = fabsf((after - avf)  / Wpf);
        float g2w = fabsf((avc1 - after) / Wpf);
        float wq[4];
        wq[0] = g1w * fabsf(after - avf);
        wq[1] = g1w * fabsf(avf1 - after);
        wq[2] = g2w * fabsf(after - avc1);
        wq[3] = g2w * fabsf(avc  - after);
        int iq[4] = {(int)avf, (int)avf1, (int)avc1, (int)avc};
        int lo = min(min(iq[0], iq[1]), min(iq[2], iq[3]));
        float w3[3] = {0.f, 0.f, 0.f};
        #pragma unroll
        for (int j = 0; j < 4; j++) w3[iq[j] - lo] += wq[j];
        int vbase = -1, firstslot = 0;
        #pragma unroll
        for (int s = 0; s < 3; s++) {
            int id = lo + s;
            int rr = id / Wp, c2 = id - rr * Wp;
            bool valid = (rr >= 1 && rr <= Hh && c2 >= 1 && c2 <= Ww);
            if (!valid) w3[s] = 0.f;
            else if (w3[s] != 0.f && vbase < 0) {
                vbase = (rr - 1) * Ww + (c2 - 1);
                firstslot = s;
            }
        }
        float fw[3] = {0.f, 0.f, 0.f};
        int bidx = 0;
        if (vbase >= 0) {
            int base = vbase - firstslot;
            bidx = min(max(base, 0), HW - 3);
            #pragma unroll
            for (int s = 0; s < 3; s++)
                if (w3[s] != 0.f) fw[(base + s) - bidx] += w3[s];
        }
        g_tbase[k * HW + p] = bidx;
        g_tw3[(k * 3 + 0) * HW + p] = fw[0];
        g_tw3[(k * 3 + 1) * HW + p] = fw[1];
        g_tw3[(k * 3 + 2) * HW + p] = fw[2];
    }
}

// ---------------- 2) deformable gather-contraction ----------------
__global__ void gather_kernel(const float* __restrict__ x,
                              const float* __restrict__ ro /* (CIN,9) */) {
    __shared__ int   s_base[9 * 64];
    __shared__ float s_w[27 * 64];
    __shared__ float s_ro[64 * 9];
    int p0 = blockIdx.x * 64;
    int c0 = blockIdx.y * 64;
    int tid = threadIdx.x;
    for (int i = tid; i < 9 * 64; i += 256) {
        int t = i >> 6, px = i & 63;
        s_base[i] = g_tbase[t * HW + p0 + px];
    }
    for (int i = tid; i < 27 * 64; i += 256) {
        int t = i >> 6, px = i & 63;
        s_w[i] = g_tw3[t * HW + p0 + px];
    }
    for (int i = tid; i < 64 * 9; i += 256) {
        int cl = i / 9, k = i - cl * 9;
        s_ro[i] = ro[(c0 + cl) * 9 + k];
    }
    __syncthreads();
    int px = tid & 63;
    int cg = tid >> 6;
    int p = p0 + px;
    #pragma unroll 1
    for (int ci = 0; ci < 16; ci++) {
        int cl = cg * 16 + ci;
        int c  = c0 + cl;
        const float* xp = x + (size_t)c * HW;
        float acc = 0.f;
        #pragma unroll
        for (int k = 0; k < 9; k++) {
            float rk = s_ro[cl * 9 + k];
            int   b  = s_base[k * 64 + px];
            float w0 = s_w[(k * 3 + 0) * 64 + px];
            float w1 = s_w[(k * 3 + 1) * 64 + px];
            float w2 = s_w[(k * 3 + 2) * 64 + px];
            const float* xb = xp + b;
            float s = fmaf(w0, __ldg(xb + 0),
                      fmaf(w1, __ldg(xb + 1),
                           w2 * __ldg(xb + 2)));
            acc = fmaf(rk, s, acc);
        }
        g_y0[(size_t)c * HW + p] = acc;
    }
}

// ---------------- 3) fp32 GEMM + fused BN-stat epilogue ----------------
// C[128,N] = A[128,K] * B[K,N]; 64x64 tile, BK=16, 256 threads, 4x4 microtile.
// Double-buffered smem (1 sync/stage) + packed fma.rn.f32x2 inner loop.
__global__ void gemm_kernel(const float* __restrict__ A, const float* __restrict__ B,
                            float* __restrict__ C, int K,
                            float* __restrict__ sum, float* __restrict__ sum2) {
    __shared__ float As[2][16][68];   // 68: keeps As[.][k][4*ty] 16B-aligned
    __shared__ float Bs[2][16][64];
    const int N = HW;
    int bn = blockIdx.x * 64, bm = blockIdx.y * 64;
    int tid = threadIdx.x;
    int tx = tid & 15, ty = tid >> 4;
    int am  = tid >> 2;             // A row within tile
    int akk = (tid & 3) * 4;        // A k-offset
    int bk  = tid >> 4;             // B k row
    int bnn = (tid & 15) * 4;       // B col group
    const float* Ap = &A[(size_t)(bm + am) * K + akk];
    const float* Bp = &B[(size_t)bk * N + bn + bnn];

    // stage 0 load
    float4 av = *(const float4*)Ap;
    float4 bv = *(const float4*)Bp;
    As[0][akk + 0][am] = av.x; As[0][akk + 1][am] = av.y;
    As[0][akk + 2][am] = av.z; As[0][akk + 3][am] = av.w;
    *(float4*)&Bs[0][bk][bnn] = bv;
    __syncthreads();

    unsigned long long acc2[4][2];
    #pragma unroll
    for (int i = 0; i < 4; i++) { acc2[i][0] = 0ull; acc2[i][1] = 0ull; }

    int nstage = K / 16;
    for (int s = 0; s < nstage; s++) {
        int buf = s & 1;
        bool more = (s + 1 < nstage);
        if (more) {                       // prefetch next stage into regs
            int k0 = (s + 1) * 16;
            av = *(const float4*)(Ap + k0);
            bv = *(const float4*)(Bp + (size_t)k0 * N);
        }
        #pragma unroll
        for (int k = 0; k < 16; k++) {
            float4 a4 = *(const float4*)&As[buf][k][ty * 4];
            ulonglong2 bb = *(const ulonglong2*)&Bs[buf][k][tx * 4];
            unsigned long long aa;
            PACKDUP(aa, a4.x); FFMA2(acc2[0][0], aa, bb.x); FFMA2(acc2[0][1], aa, bb.y);
            PACKDUP(aa, a4.y); FFMA2(acc2[1][0], aa, bb.x); FFMA2(acc2[1][1], aa, bb.y);
            PACKDUP(aa, a4.z); FFMA2(acc2[2][0], aa, bb.x); FFMA2(acc2[2][1], aa, bb.y);
            PACKDUP(aa, a4.w); FFMA2(acc2[3][0], aa, bb.x); FFMA2(acc2[3][1], aa, bb.y);
        }
        if (more) {                       // store into the other buffer, single sync
            int nb = buf ^ 1;
            As[nb][akk + 0][am] = av.x; As[nb][akk + 1][am] = av.y;
            As[nb][akk + 2][am] = av.z; As[nb][akk + 3][am] = av.w;
            *(float4*)&Bs[nb][bk][bnn] = bv;
            __syncthreads();
        }
    }

    // unpack accumulators
    float acc[4][4];
    #pragma unroll
    for (int i = 0; i < 4; i++) {
        float2 lo = *(float2*)&acc2[i][0];
        float2 hi = *(float2*)&acc2[i][1];
        acc[i][0] = lo.x; acc[i][1] = lo.y; acc[i][2] = hi.x; acc[i][3] = hi.y;
    }
    #pragma unroll
    for (int i = 0; i < 4; i++) {
        int m = bm + ty * 4 + i;
        float4 v = make_float4(acc[i][0], acc[i][1], acc[i][2], acc[i][3]);
        *(float4*)&C[(size_t)m * N + bn + tx * 4] = v;
        float s  = acc[i][0] + acc[i][1] + acc[i][2] + acc[i][3];
        float s2 = fmaf(acc[i][0], acc[i][0],
                   fmaf(acc[i][1], acc[i][1],
                   fmaf(acc[i][2], acc[i][2], acc[i][3] * acc[i][3])));
        #pragma unroll
        for (int off = 8; off > 0; off >>= 1) {
            s  += __shfl_down_sync(0xffffffffu, s,  off, 16);
            s2 += __shfl_down_sync(0xffffffffu, s2, off, 16);
        }
        if (tx == 0) {
            atomicAdd(&sum[m],  s);
            atomicAdd(&sum2[m], s2);
        }
    }
}

// ---------------- BN scale/bias from accumulated stats ----------------
__device__ __forceinline__ void bn_coeffs(int c, const float* sum, const float* sum2,
                                          const float* __restrict__ g,
                                          const float* __restrict__ b,
                                          float& sc, float& bi) {
    float mean = sum[c] * (1.f / (float)HW);
    float var  = sum2[c] * (1.f / (float)HW) - mean * mean;
    float rstd = rsqrtf(var + EPSv);
    sc = g[c] * rstd;
    bi = b[c] - mean * sc;
}

__device__ __forceinline__ float bn_leaky(float v, float sc, float bi) {
    float y = fmaf(v, sc, bi);
    return y >= 0.f ? y : LEAK * y;
}

// ---------------- 4) depthwise 3x3 with fused BN+leaky on input ----------------
__global__ void dw_kernel(const float* __restrict__ in, const float* __restrict__ dw,
                          float* __restrict__ out,
                          const float* __restrict__ sum, const float* __restrict__ sum2,
                          const float* __restrict__ g, const float* __restrict__ b) {
    int c = blockIdx.y;
    int p = blockIdx.x * 256 + threadIdx.x;
    if (p >= HW) return;
    int r = p / Ww, col = p - r * Ww;
    float sc, bi;
    bn_coeffs(c, sum, sum2, g, b, sc, bi);
    float wl[9];
    #pragma unroll
    for (int i = 0; i < 9; i++) wl[i] = dw[c * 9 + i];
    const float* ip = in + (size_t)c * HW;
    float acc = 0.f;
    #pragma unroll
    for (int dy = -1; dy <= 1; dy++) {
        int rr = r + dy;
        if (rr < 0 || rr >= Hh) continue;
        #pragma unroll
        for (int dx = -1; dx <= 1; dx++) {
            int cc = col + dx;
            if (cc < 0 || cc >= Ww) continue;
            float v = bn_leaky(ip[rr * Ww + cc], sc, bi);
            acc = fmaf(v, wl[(dy + 1) * 3 + (dx + 1)], acc);
        }
    }
    out[(size_t)c * HW + p] = acc;
}

// ---------------- 5) final BN+leaky apply (vectorized) ----------------
__global__ void apply_kernel(const float* __restrict__ in, float* __restrict__ out,
                             const float* __restrict__ sum, const float* __restrict__ sum2,
                             const float* __restrict__ g, const float* __restrict__ b) {
    int i = blockIdx.x * 256 + threadIdx.x;       // float4 index
    if (i >= COUT * HW / 4) return;
    int c = (i * 4) / HW;                          // HW % 4 == 0 -> uniform in vec
    float sc, bi;
    bn_coeffs(c, sum, sum2, g, b, sc, bi);
    float4 v = ((const float4*)in)[i];
    v.x = bn_leaky(v.x, sc, bi);
    v.y = bn_leaky(v.y, sc, bi);
    v.z = bn_leaky(v.z, sc, bi);
    v.w = bn_leaky(v.w, sc, bi);
    ((float4*)out)[i] = v;
}

// ---------------- launch ----------------
extern "C" void kernel_launch(void* const* d_in, const int* in_sizes, int n_in,
                              void* d_out, int out_size) {
    const float* x        = (const float*)d_in[0];
    const float* x_range  = (const float*)d_in[1];
    const float* range_o  = (const float*)d_in[2];
    const float* w_reduce = (const float*)d_in[3];
    const float* g_r      = (const float*)d_in[4];
    const float* b_r      = (const float*)d_in[5];
    const float* dw1      = (const float*)d_in[6];
    const float* pw1      = (const float*)d_in[7];
    const float* g1       = (const float*)d_in[8];
    const float* b1       = (const float*)d_in[9];
    const float* dw2      = (const float*)d_in[10];
    const float* pw2      = (const float*)d_in[11];
    const float* g2       = (const float*)d_in[12];
    const float* b2       = (const float*)d_in[13];
    float* out = (float*)d_out;

    float *t1, *t2, *t3, *y0, *sumb, *sum2b;
    cudaGetSymbolAddress((void**)&t1, g_t1);
    cudaGetSymbolAddress((void**)&t2, g_t2);
    cudaGetSymbolAddress((void**)&t3, g_t3);
    cudaGetSymbolAddress((void**)&y0, g_y0);
    cudaGetSymbolAddress((void**)&sumb, g_sum);
    cudaGetSymbolAddress((void**)&sum2b, g_sum2);
    float* s0  = sumb;            float* q0 = sum2b;
    float* s1  = sumb + COUT;     float* q1 = sum2b + COUT;
    float* s2  = sumb + 2*COUT;   float* q2 = sum2b + 2*COUT;

    init_kernel<<<1, 128>>>();
    tab_kernel<<<(HW + 255) / 256, 256>>>(x_range);
    gather_kernel<<<dim3(HW / 64, CIN / 64), 256>>>(x, range_o);

    gemm_kernel<<<dim3(HW / 64, COUT / 64), 256>>>(w_reduce, y0, t1, CIN, s0, q0);
    dw_kernel<<<dim3((HW + 255) / 256, COUT), 256>>>(t1, dw1, t2, s0, q0, g_r, b_r);

    gemm_kernel<<<dim3(HW / 64, COUT / 64), 256>>>(pw1, t2, t3, COUT, s1, q1);
    dw_kernel<<<dim3((HW + 255) / 256, COUT), 256>>>(t3, dw2, t2, s1, q1, g1, b1);

    gemm_kernel<<<dim3(HW / 64, COUT / 64), 256>>>(pw2, t2, t1, COUT, s2, q2);
    apply_kernel<<<(COUT * HW / 4 + 255) / 256, 256>>>(t1, out, s2, q2, g2, b2);
}

// round 7
// speedup vs baseline: 1.5386x; 1.2118x over previous
#include <cuda_runtime.h>
#include <cuda_bf16.h>
#include <math.h>

// Problem constants
#define Bq    1
#define CIN   256
#define COUT  128
#define Hh    64
#define Ww    192
#define HW    (Hh*Ww)          // 12288
#define Hp    (Hh+2)           // 66
#define Wp    (Ww+2)           // 194
#define Pp    (Hp*Wp)          // 12804
#define EPSv  1e-5f
#define LEAK  0.01f

// ---------------- scratch (static __device__ — no allocation) ----------------
__device__ int   g_tbase[9 * HW];        // per-tap window base index into UNPADDED x
__device__ float g_tw3[27 * HW];         // per-tap 3 positional weights
__device__ float g_y0[CIN * HW];         // deformable-gather output (12.6 MB)
__device__ float g_t1[COUT * HW];
__device__ float g_t2[COUT * HW];
__device__ float g_t3[COUT * HW];
__device__ float g_sum[3][COUT];         // per-stage channel sums
__device__ float g_sum2[3][COUT];        // per-stage channel sum-of-squares

// ---- packed fp32x2 helpers (Blackwell FFMA2) ----
#define FFMA2(d, a, b) \
    asm("fma.rn.f32x2 %0, %1, %2, %0;" : "+l"(d) : "l"(a), "l"(b))
#define PACKDUP(d, x) \
    asm("mov.b64 %0, {%1, %1};" : "=l"(d) : "r"(__float_as_uint(x)))

// ---------------- 0) zero the stat accumulators ----------------
__global__ void init_kernel() {
    int i = threadIdx.x;
    if (i < COUT) {
        #pragma unroll
        for (int s = 0; s < 3; s++) { g_sum[s][i] = 0.f; g_sum2[s][i] = 0.f; }
    }
}

// ---------------- 1) per-pixel gather tables (window-compressed) ----------------
__global__ void tab_kernel(const float* __restrict__ xr) {
    int p = blockIdx.x * 256 + threadIdx.x;
    if (p >= HW) return;
    float off = 3.0f * (1.0f / (1.0f + expf(-xr[p])));
    int r = p / Ww, cc = p - r * Ww;
    float v0 = (float)((r + 1) * Wp + (cc + 1));
    const float xo9[9] = {-1,0,1,-1,0,1,-1,0,1};
    const float yo9[9] = {-1,-1,-1,0,0,0,1,1,1};
    const float Pm1 = (float)(Pp - 1);
    const float Wpf = (float)Wp;
    #pragma unroll
    for (int k = 0; k < 9; k++) {
        float xo = xo9[k], yo = yo9[k];
        float pre  = v0 + xo + yo * Wpf;                       // exact ints in fp32
        float offv = __fadd_rn(__fmul_rn(off, xo), yo * Wpf);  // match mul-then-add
        float after = __fadd_rn(pre, offv);
        float avf  = fminf(fmaxf(pre + floorf(offv), 0.f), Pm1);
        float avf1 = fminf(fmaxf(avf + xo, 0.f), Pm1);
        float avc  = fminf(fmaxf(pre + ceilf(offv), 0.f), Pm1);
        float avc1 = fminf(fmaxf(avc + xo, 0.f), Pm1);
        float g1w = fabsf((after - avf)  / Wpf);
        float g2w = fabsf((avc1 - after) / Wpf);
        float wq[4];
        wq[0] = g1w * fabsf(after - avf);
        wq[1] = g1w * fabsf(avf1 - after);
        wq[2] = g2w * fabsf(after - avc1);
        wq[3] = g2w * fabsf(avc  - after);
        int iq[4] = {(int)avf, (int)avf1, (int)avc1, (int)avc};
        int lo = min(min(iq[0], iq[1]), min(iq[2], iq[3]));
        float w3[3] = {0.f, 0.f, 0.f};
        #pragma unroll
        for (int j = 0; j < 4; j++) w3[iq[j] - lo] += wq[j];
        int vbase = -1, firstslot = 0;
        #pragma unroll
        for (int s = 0; s < 3; s++) {
            int id = lo + s;
            int rr = id / Wp, c2 = id - rr * Wp;
            bool valid = (rr >= 1 && rr <= Hh && c2 >= 1 && c2 <= Ww);
            if (!valid) w3[s] = 0.f;
            else if (w3[s] != 0.f && vbase < 0) {
                vbase = (rr - 1) * Ww + (c2 - 1);
                firstslot = s;
            }
        }
        float fw[3] = {0.f, 0.f, 0.f};
        int bidx = 0;
        if (vbase >= 0) {
            int base = vbase - firstslot;
            bidx = min(max(base, 0), HW - 3);
            #pragma unroll
            for (int s = 0; s < 3; s++)
                if (w3[s] != 0.f) fw[(base + s) - bidx] += w3[s];
        }
        g_tbase[k * HW + p] = bidx;
        g_tw3[(k * 3 + 0) * HW + p] = fw[0];
        g_tw3[(k * 3 + 1) * HW + p] = fw[1];
        g_tw3[(k * 3 + 2) * HW + p] = fw[2];
    }
}

// ---------------- 2) deformable gather-contraction (taps-outer) ----------------
// block: 64 pixels x 64 channels, 256 threads (64 px x 4 channel-groups of 16).
// Per tap: base/w are channel-independent (4 LDS), ro read as 4x LDS.128.
__global__ void gather_kernel(const float* __restrict__ x,
                              const float* __restrict__ ro /* (CIN,9) */) {
    __shared__ int   s_base[9 * 64];
    __shared__ float s_w[27 * 64];
    __shared__ __align__(16) float s_ro[9 * 64];  // tap-major: [k][cl]
    int p0 = blockIdx.x * 64;
    int c0 = blockIdx.y * 64;
    int tid = threadIdx.x;
    for (int i = tid; i < 9 * 64; i += 256) {
        int t = i >> 6, px = i & 63;
        s_base[i] = g_tbase[t * HW + p0 + px];
    }
    for (int i = tid; i < 27 * 64; i += 256) {
        int t = i >> 6, px = i & 63;
        s_w[i] = g_tw3[t * HW + p0 + px];
    }
    for (int i = tid; i < 9 * 64; i += 256) {
        int k = i >> 6, cl = i & 63;
        s_ro[i] = ro[(c0 + cl) * 9 + k];
    }
    __syncthreads();
    int px = tid & 63;
    int cg = tid >> 6;
    int p = p0 + px;
    int cbase = c0 + cg * 16;
    const float* xc = x + (size_t)cbase * HW;

    float acc[16];
    #pragma unroll
    for (int i = 0; i < 16; i++) acc[i] = 0.f;

    #pragma unroll
    for (int k = 0; k < 9; k++) {
        int   b  = s_base[k * 64 + px];
        float w0 = s_w[(k * 3 + 0) * 64 + px];
        float w1 = s_w[(k * 3 + 1) * 64 + px];
        float w2 = s_w[(k * 3 + 2) * 64 + px];
        float4 r0 = *(const float4*)&s_ro[k * 64 + cg * 16 + 0];
        float4 r1 = *(const float4*)&s_ro[k * 64 + cg * 16 + 4];
        float4 r2 = *(const float4*)&s_ro[k * 64 + cg * 16 + 8];
        float4 r3 = *(const float4*)&s_ro[k * 64 + cg * 16 + 12];
        float rk[16] = {r0.x, r0.y, r0.z, r0.w, r1.x, r1.y, r1.z, r1.w,
                        r2.x, r2.y, r2.z, r2.w, r3.x, r3.y, r3.z, r3.w};
        const float* xb = xc + b;
        #pragma unroll
        for (int ci = 0; ci < 16; ci++) {
            const float* xp = xb + (size_t)ci * HW;
            float s = fmaf(w0, __ldg(xp + 0),
                      fmaf(w1, __ldg(xp + 1),
                           w2 * __ldg(xp + 2)));
            acc[ci] = fmaf(rk[ci], s, acc[ci]);
        }
    }
    #pragma unroll
    for (int ci = 0; ci < 16; ci++)
        g_y0[(size_t)(cbase + ci) * HW + p] = acc[ci];
}

// ---------------- 3) fp32 GEMM + fused BN-stat epilogue ----------------
// C[128,N] = A[128,K] * B[K,N]; 64x64 tile, BK=16, 256 threads, 4x4 microtile.
// Double-buffered smem (1 sync/stage) + packed fma.rn.f32x2 inner loop.
__global__ void gemm_kernel(const float* __restrict__ A, const float* __restrict__ B,
                            float* __restrict__ C, int K,
                            float* __restrict__ sum, float* __restrict__ sum2) {
    __shared__ float As[2][16][68];   // 68: keeps As[.][k][4*ty] 16B-aligned
    __shared__ float Bs[2][16][64];
    const int N = HW;
    int bn = blockIdx.x * 64, bm = blockIdx.y * 64;
    int tid = threadIdx.x;
    int tx = tid & 15, ty = tid >> 4;
    int am  = tid >> 2;             // A row within tile
    int akk = (tid & 3) * 4;        // A k-offset
    int bk  = tid >> 4;             // B k row
    int bnn = (tid & 15) * 4;       // B col group
    const float* Ap = &A[(size_t)(bm + am) * K + akk];
    const float* Bp = &B[(size_t)bk * N + bn + bnn];

    float4 av = *(const float4*)Ap;
    float4 bv = *(const float4*)Bp;
    As[0][akk + 0][am] = av.x; As[0][akk + 1][am] = av.y;
    As[0][akk + 2][am] = av.z; As[0][akk + 3][am] = av.w;
    *(float4*)&Bs[0][bk][bnn] = bv;
    __syncthreads();

    unsigned long long acc2[4][2];
    #pragma unroll
    for (int i = 0; i < 4; i++) { acc2[i][0] = 0ull; acc2[i][1] = 0ull; }

    int nstage = K / 16;
    for (int s = 0; s < nstage; s++) {
        int buf = s & 1;
        bool more = (s + 1 < nstage);
        if (more) {
            int k0 = (s + 1) * 16;
            av = *(const float4*)(Ap + k0);
            bv = *(const float4*)(Bp + (size_t)k0 * N);
        }
        #pragma unroll
        for (int k = 0; k < 16; k++) {
            float4 a4 = *(const float4*)&As[buf][k][ty * 4];
            ulonglong2 bb = *(const ulonglong2*)&Bs[buf][k][tx * 4];
            unsigned long long aa;
            PACKDUP(aa, a4.x); FFMA2(acc2[0][0], aa, bb.x); FFMA2(acc2[0][1], aa, bb.y);
            PACKDUP(aa, a4.y); FFMA2(acc2[1][0], aa, bb.x); FFMA2(acc2[1][1], aa, bb.y);
            PACKDUP(aa, a4.z); FFMA2(acc2[2][0], aa, bb.x); FFMA2(acc2[2][1], aa, bb.y);
            PACKDUP(aa, a4.w); FFMA2(acc2[3][0], aa, bb.x); FFMA2(acc2[3][1], aa, bb.y);
        }
        if (more) {
            int nb = buf ^ 1;
            As[nb][akk + 0][am] = av.x; As[nb][akk + 1][am] = av.y;
            As[nb][akk + 2][am] = av.z; As[nb][akk + 3][am] = av.w;
            *(float4*)&Bs[nb][bk][bnn] = bv;
            __syncthreads();
        }
    }

    float acc[4][4];
    #pragma unroll
    for (int i = 0; i < 4; i++) {
        float2 lo = *(float2*)&acc2[i][0];
        float2 hi = *(float2*)&acc2[i][1];
        acc[i][0] = lo.x; acc[i][1] = lo.y; acc[i][2] = hi.x; acc[i][3] = hi.y;
    }
    #pragma unroll
    for (int i = 0; i < 4; i++) {
        int m = bm + ty * 4 + i;
        float4 v = make_float4(acc[i][0], acc[i][1], acc[i][2], acc[i][3]);
        *(float4*)&C[(size_t)m * N + bn + tx * 4] = v;
        float s  = acc[i][0] + acc[i][1] + acc[i][2] + acc[i][3];
        float s2 = fmaf(acc[i][0], acc[i][0],
                   fmaf(acc[i][1], acc[i][1],
                   fmaf(acc[i][2], acc[i][2], acc[i][3] * acc[i][3])));
        #pragma unroll
        for (int off = 8; off > 0; off >>= 1) {
            s  += __shfl_down_sync(0xffffffffu, s,  off, 16);
            s2 += __shfl_down_sync(0xffffffffu, s2, off, 16);
        }
        if (tx == 0) {
            atomicAdd(&sum[m],  s);
            atomicAdd(&sum2[m], s2);
        }
    }
}

// ---------------- BN scale/bias from accumulated stats ----------------
__device__ __forceinline__ void bn_coeffs(int c, const float* sum, const float* sum2,
                                          const float* __restrict__ g,
                                          const float* __restrict__ b,
                                          float& sc, float& bi) {
    float mean = sum[c] * (1.f / (float)HW);
    float var  = sum2[c] * (1.f / (float)HW) - mean * mean;
    float rstd = rsqrtf(var + EPSv);
    sc = g[c] * rstd;
    bi = b[c] - mean * sc;
}

__device__ __forceinline__ float bn_leaky(float v, float sc, float bi) {
    float y = fmaf(v, sc, bi);
    return y >= 0.f ? y : LEAK * y;
}

// ---------------- 4) depthwise 3x3, 4 px/thread, fused BN+leaky on input ----------------
__global__ void dw_kernel(const float* __restrict__ in, const float* __restrict__ dw,
                          float* __restrict__ out,
                          const float* __restrict__ sum, const float* __restrict__ sum2,
                          const float* __restrict__ g, const float* __restrict__ b) {
    int c = blockIdx.y;
    int q = blockIdx.x * 256 + threadIdx.x;        // float4 output index
    if (q >= HW / 4) return;
    int p0 = q * 4;
    int r = p0 / Ww, col0 = p0 - r * Ww;           // col0 multiple of 4 (Ww%4==0)
    float sc, bi;
    bn_coeffs(c, sum, sum2, g, b, sc, bi);
    float wl[9];
    #pragma unroll
    for (int i = 0; i < 9; i++) wl[i] = dw[c * 9 + i];
    const float* ip = in + (size_t)c * HW;
    float vin[3][6];
    #pragma unroll
    for (int t = 0; t < 3; t++) {
        int rr = r + t - 1;
        bool rowok = (rr >= 0 && rr < Hh);
        #pragma unroll
        for (int j = 0; j < 6; j++) {
            int cc = col0 - 1 + j;
            float v = 0.f;
            if (rowok && cc >= 0 && cc < Ww)
                v = bn_leaky(ip[rr * Ww + cc], sc, bi);
            vin[t][j] = v;
        }
    }
    float4 o;
    float* op = &o.x;
    #pragma unroll
    for (int i = 0; i < 4; i++) {
        float acc = 0.f;
        #pragma unroll
        for (int t = 0; t < 3; t++)
            #pragma unroll
            for (int dx = 0; dx < 3; dx++)
                acc = fmaf(vin[t][i + dx], wl[t * 3 + dx], acc);
        op[i] = acc;
    }
    *(float4*)&out[(size_t)c * HW + p0] = o;
}

// ---------------- 5) final BN+leaky apply (vectorized) ----------------
__global__ void apply_kernel(const float* __restrict__ in, float* __restrict__ out,
                             const float* __restrict__ sum, const float* __restrict__ sum2,
                             const float* __restrict__ g, const float* __restrict__ b) {
    int i = blockIdx.x * 256 + threadIdx.x;       // float4 index
    if (i >= COUT * HW / 4) return;
    int c = (i * 4) / HW;                          // HW % 4 == 0 -> uniform in vec
    float sc, bi;
    bn_coeffs(c, sum, sum2, g, b, sc, bi);
    float4 v = ((const float4*)in)[i];
    v.x = bn_leaky(v.x, sc, bi);
    v.y = bn_leaky(v.y, sc, bi);
    v.z = bn_leaky(v.z, sc, bi);
    v.w = bn_leaky(v.w, sc, bi);
    ((float4*)out)[i] = v;
}

// ---------------- launch ----------------
extern "C" void kernel_launch(void* const* d_in, const int* in_sizes, int n_in,
                              void* d_out, int out_size) {
    const float* x        = (const float*)d_in[0];
    const float* x_range  = (const float*)d_in[1];
    const float* range_o  = (const float*)d_in[2];
    const float* w_reduce = (const float*)d_in[3];
    const float* g_r      = (const float*)d_in[4];
    const float* b_r      = (const float*)d_in[5];
    const float* dw1      = (const float*)d_in[6];
    const float* pw1      = (const float*)d_in[7];
    const float* g1       = (const float*)d_in[8];
    const float* b1       = (const float*)d_in[9];
    const float* dw2      = (const float*)d_in[10];
    const float* pw2      = (const float*)d_in[11];
    const float* g2       = (const float*)d_in[12];
    const float* b2       = (const float*)d_in[13];
    float* out = (float*)d_out;

    float *t1, *t2, *t3, *y0, *sumb, *sum2b;
    cudaGetSymbolAddress((void**)&t1, g_t1);
    cudaGetSymbolAddress((void**)&t2, g_t2);
    cudaGetSymbolAddress((void**)&t3, g_t3);
    cudaGetSymbolAddress((void**)&y0, g_y0);
    cudaGetSymbolAddress((void**)&sumb, g_sum);
    cudaGetSymbolAddress((void**)&sum2b, g_sum2);
    float* s0  = sumb;            float* q0 = sum2b;
    float* s1  = sumb + COUT;     float* q1 = sum2b + COUT;
    float* s2  = sumb + 2*COUT;   float* q2 = sum2b + 2*COUT;

    init_kernel<<<1, 128>>>();
    tab_kernel<<<(HW + 255) / 256, 256>>>(x_range);
    gather_kernel<<<dim3(HW / 64, CIN / 64), 256>>>(x, range_o);

    gemm_kernel<<<dim3(HW / 64, COUT / 64), 256>>>(w_reduce, y0, t1, CIN, s0, q0);
    dw_kernel<<<dim3(HW / 4 / 256, COUT), 256>>>(t1, dw1, t2, s0, q0, g_r, b_r);

    gemm_kernel<<<dim3(HW / 64, COUT / 64), 256>>>(pw1, t2, t3, COUT, s1, q1);
    dw_kernel<<<dim3(HW / 4 / 256, COUT), 256>>>(t3, dw2, t2, s1, q1, g1, b1);

    gemm_kernel<<<dim3(HW / 64, COUT / 64), 256>>>(pw2, t2, t1, COUT, s2, q2);
    apply_kernel<<<(COUT * HW / 4 + 255) / 256, 256>>>(t1, out, s2, q2, g2, b2);
}

// round 8
// speedup vs baseline: 1.5673x; 1.0187x over previous
#include <cuda_runtime.h>
#include <cuda_bf16.h>
#include <math.h>
#include <stdint.h>

// Problem constants
#define CIN   256
#define COUT  128
#define Hh    64
#define Ww    192
#define HW    (Hh*Ww)          // 12288
#define Hp    (Hh+2)           // 66
#define Wp    (Ww+2)           // 194
#define Pp    (Hp*Wp)          // 12804
#define EPSv  1e-5f
#define LEAK  0.01f

// ---------------- scratch (static __device__ — no allocation) ----------------
__device__ int   g_tbase[9 * HW];
__device__ float g_tw3[27 * HW];
__device__ __nv_bfloat16 g_y0h[CIN * HW];   // gather output, bf16 hi plane
__device__ __nv_bfloat16 g_y0l[CIN * HW];   // gather output, bf16 lo plane
__device__ float g_t1[COUT * HW];           // GEMM fp32 outputs
__device__ float g_t3[COUT * HW];
__device__ __nv_bfloat16 g_t2h[COUT * HW];  // dw output hi/lo planes
__device__ __nv_bfloat16 g_t2l[COUT * HW];
__device__ float g_sum[3][COUT];
__device__ float g_sum2[3][COUT];

__device__ __forceinline__ void split_bf16(float v, __nv_bfloat16& h, __nv_bfloat16& l) {
    h = __float2bfloat16(v);
    l = __float2bfloat16(v - __bfloat162float(h));
}

// ---------------- 0) zero the stat accumulators ----------------
__global__ void init_kernel() {
    int i = threadIdx.x;
    if (i < COUT) {
        #pragma unroll
        for (int s = 0; s < 3; s++) { g_sum[s][i] = 0.f; g_sum2[s][i] = 0.f; }
    }
}

// ---------------- 1) per-pixel gather tables (window-compressed) ----------------
__global__ void tab_kernel(const float* __restrict__ xr) {
    int p = blockIdx.x * 256 + threadIdx.x;
    if (p >= HW) return;
    float off = 3.0f * (1.0f / (1.0f + expf(-xr[p])));
    int r = p / Ww, cc = p - r * Ww;
    float v0 = (float)((r + 1) * Wp + (cc + 1));
    const float xo9[9] = {-1,0,1,-1,0,1,-1,0,1};
    const float yo9[9] = {-1,-1,-1,0,0,0,1,1,1};
    const float Pm1 = (float)(Pp - 1);
    const float Wpf = (float)Wp;
    #pragma unroll
    for (int k = 0; k < 9; k++) {
        float xo = xo9[k], yo = yo9[k];
        float pre  = v0 + xo + yo * Wpf;
        float offv = __fadd_rn(__fmul_rn(off, xo), yo * Wpf);
        float after = __fadd_rn(pre, offv);
        float avf  = fminf(fmaxf(pre + floorf(offv), 0.f), Pm1);
        float avf1 = fminf(fmaxf(avf + xo, 0.f), Pm1);
        float avc  = fminf(fmaxf(pre + ceilf(offv), 0.f), Pm1);
        float avc1 = fminf(fmaxf(avc + xo, 0.f), Pm1);
        float g1w = fabsf((after - avf)  / Wpf);
        float g2w = fabsf((avc1 - after) / Wpf);
        float wq[4];
        wq[0] = g1w * fabsf(after - avf);
        wq[1] = g1w * fabsf(avf1 - after);
        wq[2] = g2w * fabsf(after - avc1);
        wq[3] = g2w * fabsf(avc  - after);
        int iq[4] = {(int)avf, (int)avf1, (int)avc1, (int)avc};
        int lo = min(min(iq[0], iq[1]), min(iq[2], iq[3]));
        float w3[3] = {0.f, 0.f, 0.f};
        #pragma unroll
        for (int j = 0; j < 4; j++) w3[iq[j] - lo] += wq[j];
        int vbase = -1, firstslot = 0;
        #pragma unroll
        for (int s = 0; s < 3; s++) {
            int id = lo + s;
            int rr = id / Wp, c2 = id - rr * Wp;
            bool valid = (rr >= 1 && rr <= Hh && c2 >= 1 && c2 <= Ww);
            if (!valid) w3[s] = 0.f;
            else if (w3[s] != 0.f && vbase < 0) {
                vbase = (rr - 1) * Ww + (c2 - 1);
                firstslot = s;
            }
        }
        float fw[3] = {0.f, 0.f, 0.f};
        int bidx = 0;
        if (vbase >= 0) {
            int base = vbase - firstslot;
            bidx = min(max(base, 0), HW - 3);
            #pragma unroll
            for (int s = 0; s < 3; s++)
                if (w3[s] != 0.f) fw[(base + s) - bidx] += w3[s];
        }
        g_tbase[k * HW + p] = bidx;
        g_tw3[(k * 3 + 0) * HW + p] = fw[0];
        g_tw3[(k * 3 + 1) * HW + p] = fw[1];
        g_tw3[(k * 3 + 2) * HW + p] = fw[2];
    }
}

// ---------------- 2) deformable gather-contraction (taps-outer) ----------------
__global__ void gather_kernel(const float* __restrict__ x,
                              const float* __restrict__ ro /* (CIN,9) */) {
    __shared__ int   s_base[9 * 64];
    __shared__ float s_w[27 * 64];
    __shared__ __align__(16) float s_ro[9 * 64];
    int p0 = blockIdx.x * 64;
    int c0 = blockIdx.y * 64;
    int tid = threadIdx.x;
    for (int i = tid; i < 9 * 64; i += 256) {
        int t = i >> 6, px = i & 63;
        s_base[i] = g_tbase[t * HW + p0 + px];
    }
    for (int i = tid; i < 27 * 64; i += 256) {
        int t = i >> 6, px = i & 63;
        s_w[i] = g_tw3[t * HW + p0 + px];
    }
    for (int i = tid; i < 9 * 64; i += 256) {
        int k = i >> 6, cl = i & 63;
        s_ro[i] = ro[(c0 + cl) * 9 + k];
    }
    __syncthreads();
    int px = tid & 63;
    int cg = tid >> 6;
    int p = p0 + px;
    int cbase = c0 + cg * 16;
    const float* xc = x + (size_t)cbase * HW;

    float acc[16];
    #pragma unroll
    for (int i = 0; i < 16; i++) acc[i] = 0.f;

    #pragma unroll
    for (int k = 0; k < 9; k++) {
        int   b  = s_base[k * 64 + px];
        float w0 = s_w[(k * 3 + 0) * 64 + px];
        float w1 = s_w[(k * 3 + 1) * 64 + px];
        float w2 = s_w[(k * 3 + 2) * 64 + px];
        float4 r0 = *(const float4*)&s_ro[k * 64 + cg * 16 + 0];
        float4 r1 = *(const float4*)&s_ro[k * 64 + cg * 16 + 4];
        float4 r2 = *(const float4*)&s_ro[k * 64 + cg * 16 + 8];
        float4 r3 = *(const float4*)&s_ro[k * 64 + cg * 16 + 12];
        float rk[16] = {r0.x, r0.y, r0.z, r0.w, r1.x, r1.y, r1.z, r1.w,
                        r2.x, r2.y, r2.z, r2.w, r3.x, r3.y, r3.z, r3.w};
        const float* xb = xc + b;
        #pragma unroll
        for (int ci = 0; ci < 16; ci++) {
            const float* xp = xb + (size_t)ci * HW;
            float s = fmaf(w0, __ldg(xp + 0),
                      fmaf(w1, __ldg(xp + 1),
                           w2 * __ldg(xp + 2)));
            acc[ci] = fmaf(rk[ci], s, acc[ci]);
        }
    }
    #pragma unroll
    for (int ci = 0; ci < 16; ci++) {
        __nv_bfloat16 h, l;
        split_bf16(acc[ci], h, l);
        size_t o = (size_t)(cbase + ci) * HW + p;
        g_y0h[o] = h;
        g_y0l[o] = l;
    }
}

// ---------------- 3) bf16 split-precision tensor-core GEMM + BN-stat epilogue ----
// C[M=128,N=HW] = A[fp32] * B[bf16 hi/lo planes].
// CTA tile 64x64, K-chunk 16, 8 warps (warp tile 32x16), mma.sync m16n8k16.
__device__ __forceinline__ void mma_bf16(float d[4], const uint32_t a[4], const uint32_t b[2]) {
    asm volatile(
        "mma.sync.aligned.m16n8k16.row.col.f32.bf16.bf16.f32 "
        "{%0,%1,%2,%3}, {%4,%5,%6,%7}, {%8,%9}, {%10,%11,%12,%13};"
        : "=f"(d[0]), "=f"(d[1]), "=f"(d[2]), "=f"(d[3])
        : "r"(a[0]), "r"(a[1]), "r"(a[2]), "r"(a[3]),
          "r"(b[0]), "r"(b[1]),
          "f"(d[0]), "f"(d[1]), "f"(d[2]), "f"(d[3]));
}

__global__ void __launch_bounds__(256)
gemm_kernel(const float* __restrict__ A,
            const __nv_bfloat16* __restrict__ Bh,
            const __nv_bfloat16* __restrict__ Bl,
            float* __restrict__ C, int K,
            float* __restrict__ sum, float* __restrict__ sum2) {
    // smem tiles: rows padded to 9 uint32 (18 bf16) -> conflict-free frag reads
    __shared__ uint32_t Ah[64][9], Al[64][9];   // [m][k/2] bf16 pairs
    __shared__ uint32_t Bhs[64][9], Bls[64][9]; // [n][k/2] bf16 pairs
    const int N = HW;
    int bn = blockIdx.x * 64, bm = blockIdx.y * 64;
    int tid = threadIdx.x;
    int lane = tid & 31;
    int warp = tid >> 5;
    int g = lane >> 2, t = lane & 3;           // mma group/thread ids
    int m0 = (warp & 1) * 32;                  // warp m offset in tile
    int n0 = (warp >> 1) * 16;                 // warp n offset in tile

    // staging indices
    int ar = tid >> 2, akq = tid & 3;          // A: row, k-quad (4 floats)
    int bkr = tid >> 4, bn0 = (tid & 15) * 4;  // B: k row, 4 n values

    float d[2][2][4];
    #pragma unroll
    for (int i = 0; i < 2; i++)
        #pragma unroll
        for (int j = 0; j < 2; j++)
            #pragma unroll
            for (int q = 0; q < 4; q++) d[i][j][q] = 0.f;

    for (int k0 = 0; k0 < K; k0 += 16) {
        // --- stage A: 64x16 fp32 -> hi/lo bf16 pairs ---
        {
            float4 av = *(const float4*)&A[(size_t)(bm + ar) * K + k0 + akq * 4];
            __nv_bfloat16 h0, l0, h1, l1, h2, l2, h3, l3;
            split_bf16(av.x, h0, l0); split_bf16(av.y, h1, l1);
            split_bf16(av.z, h2, l2); split_bf16(av.w, h3, l3);
            __nv_bfloat162 hp0 = {h0, h1}, hp1 = {h2, h3};
            __nv_bfloat162 lp0 = {l0, l1}, lp1 = {l2, l3};
            Ah[ar][akq * 2 + 0] = *(uint32_t*)&hp0;
            Ah[ar][akq * 2 + 1] = *(uint32_t*)&hp1;
            Al[ar][akq * 2 + 0] = *(uint32_t*)&lp0;
            Al[ar][akq * 2 + 1] = *(uint32_t*)&lp1;
        }
        // --- stage B: 16k x 64n bf16 (hi and lo), transpose to [n][k] ---
        {
            const __nv_bfloat16* ph = &Bh[(size_t)(k0 + bkr) * N + bn + bn0];
            const __nv_bfloat16* pl = &Bl[(size_t)(k0 + bkr) * N + bn + bn0];
            uint2 vh = *(const uint2*)ph;
            uint2 vl = *(const uint2*)pl;
            __nv_bfloat16* bh16 = (__nv_bfloat16*)&vh;
            __nv_bfloat16* bl16 = (__nv_bfloat16*)&vl;
            #pragma unroll
            for (int j = 0; j < 4; j++) {
                ((__nv_bfloat16*)&Bhs[bn0 + j][0])[bkr] = bh16[j];
                ((__nv_bfloat16*)&Bls[bn0 + j][0])[bkr] = bl16[j];
            }
        }
        __syncthreads();

        // --- fragments + mma ---
        uint32_t ah[2][4], al[2][4], bh[2][2], bl[2][2];
        #pragma unroll
        for (int mt = 0; mt < 2; mt++) {
            int r0 = m0 + mt * 16 + g;
            ah[mt][0] = Ah[r0][t];     ah[mt][1] = Ah[r0 + 8][t];
            ah[mt][2] = Ah[r0][t + 4]; ah[mt][3] = Ah[r0 + 8][t + 4];
            al[mt][0] = Al[r0][t];     al[mt][1] = Al[r0 + 8][t];
            al[mt][2] = Al[r0][t + 4]; al[mt][3] = Al[r0 + 8][t + 4];
        }
        #pragma unroll
        for (int nt = 0; nt < 2; nt++) {
            int n = n0 + nt * 8 + g;
            bh[nt][0] = Bhs[n][t]; bh[nt][1] = Bhs[n][t + 4];
            bl[nt][0] = Bls[n][t]; bl[nt][1] = Bls[n][t + 4];
        }
        #pragma unroll
        for (int mt = 0; mt < 2; mt++)
            #pragma unroll
            for (int nt = 0; nt < 2; nt++) {
                mma_bf16(d[mt][nt], ah[mt], bh[nt]);
                mma_bf16(d[mt][nt], ah[mt], bl[nt]);
                mma_bf16(d[mt][nt], al[mt], bh[nt]);
            }
        __syncthreads();
    }

    // --- write C + fused BN stats ---
    float srow[2][2] = {{0.f, 0.f}, {0.f, 0.f}};   // [mt][row-half] sums
    float qrow[2][2] = {{0.f, 0.f}, {0.f, 0.f}};   // sum of squares
    #pragma unroll
    for (int mt = 0; mt < 2; mt++) {
        int r0 = bm + m0 + mt * 16 + g;
        #pragma unroll
        for (int nt = 0; nt < 2; nt++) {
            int col = bn + n0 + nt * 8 + 2 * t;
            float2 v0 = make_float2(d[mt][nt][0], d[mt][nt][1]);
            float2 v1 = make_float2(d[mt][nt][2], d[mt][nt][3]);
            *(float2*)&C[(size_t)r0 * N + col] = v0;
            *(float2*)&C[(size_t)(r0 + 8) * N + col] = v1;
            srow[mt][0] += v0.x + v0.y;
            srow[mt][1] += v1.x + v1.y;
            qrow[mt][0] = fmaf(v0.x, v0.x, fmaf(v0.y, v0.y, qrow[mt][0]));
            qrow[mt][1] = fmaf(v1.x, v1.x, fmaf(v1.y, v1.y, qrow[mt][1]));
        }
    }
    #pragma unroll
    for (int mt = 0; mt < 2; mt++)
        #pragma unroll
        for (int h = 0; h < 2; h++) {
            float s = srow[mt][h], q = qrow[mt][h];
            s += __shfl_down_sync(0xffffffffu, s, 1, 4);
            s += __shfl_down_sync(0xffffffffu, s, 2, 4);
            q += __shfl_down_sync(0xffffffffu, q, 1, 4);
            q += __shfl_down_sync(0xffffffffu, q, 2, 4);
            if (t == 0) {
                int row = bm + m0 + mt * 16 + g + h * 8;
                atomicAdd(&sum[row], s);
                atomicAdd(&sum2[row], q);
            }
        }
}

// ---------------- BN scale/bias from accumulated stats ----------------
__device__ __forceinline__ void bn_coeffs(int c, const float* sum, const float* sum2,
                                          const float* __restrict__ g,
                                          const float* __restrict__ b,
                                          float& sc, float& bi) {
    float mean = sum[c] * (1.f / (float)HW);
    float var  = sum2[c] * (1.f / (float)HW) - mean * mean;
    float rstd = rsqrtf(var + EPSv);
    sc = g[c] * rstd;
    bi = b[c] - mean * sc;
}

__device__ __forceinline__ float bn_leaky(float v, float sc, float bi) {
    float y = fmaf(v, sc, bi);
    return y >= 0.f ? y : LEAK * y;
}

// ---------------- 4) depthwise 3x3, 4 px/thread, fused BN+leaky, bf16-split out ----
__global__ void dw_kernel(const float* __restrict__ in, const float* __restrict__ dw,
                          __nv_bfloat16* __restrict__ outh, __nv_bfloat16* __restrict__ outl,
                          const float* __restrict__ sum, const float* __restrict__ sum2,
                          const float* __restrict__ g, const float* __restrict__ b) {
    int c = blockIdx.y;
    int q = blockIdx.x * 256 + threadIdx.x;
    if (q >= HW / 4) return;
    int p0 = q * 4;
    int r = p0 / Ww, col0 = p0 - r * Ww;
    float sc, bi;
    bn_coeffs(c, sum, sum2, g, b, sc, bi);
    float wl[9];
    #pragma unroll
    for (int i = 0; i < 9; i++) wl[i] = dw[c * 9 + i];
    const float* ip = in + (size_t)c * HW;
    float vin[3][6];
    #pragma unroll
    for (int tr = 0; tr < 3; tr++) {
        int rr = r + tr - 1;
        bool rowok = (rr >= 0 && rr < Hh);
        #pragma unroll
        for (int j = 0; j < 6; j++) {
            int cc = col0 - 1 + j;
            float v = 0.f;
            if (rowok && cc >= 0 && cc < Ww)
                v = bn_leaky(ip[rr * Ww + cc], sc, bi);
            vin[tr][j] = v;
        }
    }
    __nv_bfloat16 oh[4], ol[4];
    #pragma unroll
    for (int i = 0; i < 4; i++) {
        float acc = 0.f;
        #pragma unroll
        for (int tr = 0; tr < 3; tr++)
            #pragma unroll
            for (int dx = 0; dx < 3; dx++)
                acc = fmaf(vin[tr][i + dx], wl[tr * 3 + dx], acc);
        split_bf16(acc, oh[i], ol[i]);
    }
    *(uint2*)&outh[(size_t)c * HW + p0] = *(uint2*)oh;
    *(uint2*)&outl[(size_t)c * HW + p0] = *(uint2*)ol;
}

// ---------------- 5) final BN+leaky apply (vectorized) ----------------
__global__ void apply_kernel(const float* __restrict__ in, float* __restrict__ out,
                             const float* __restrict__ sum, const float* __restrict__ sum2,
                             const float* __restrict__ g, const float* __restrict__ b) {
    int i = blockIdx.x * 256 + threadIdx.x;
    if (i >= COUT * HW / 4) return;
    int c = (i * 4) / HW;
    float sc, bi;
    bn_coeffs(c, sum, sum2, g, b, sc, bi);
    float4 v = ((const float4*)in)[i];
    v.x = bn_leaky(v.x, sc, bi);
    v.y = bn_leaky(v.y, sc, bi);
    v.z = bn_leaky(v.z, sc, bi);
    v.w = bn_leaky(v.w, sc, bi);
    ((float4*)out)[i] = v;
}

// ---------------- launch ----------------
extern "C" void kernel_launch(void* const* d_in, const int* in_sizes, int n_in,
                              void* d_out, int out_size) {
    const float* x        = (const float*)d_in[0];
    const float* x_range  = (const float*)d_in[1];
    const float* range_o  = (const float*)d_in[2];
    const float* w_reduce = (const float*)d_in[3];
    const float* g_r      = (const float*)d_in[4];
    const float* b_r      = (const float*)d_in[5];
    const float* dw1      = (const float*)d_in[6];
    const float* pw1      = (const float*)d_in[7];
    const float* g1       = (const float*)d_in[8];
    const float* b1       = (const float*)d_in[9];
    const float* dw2      = (const float*)d_in[10];
    const float* pw2      = (const float*)d_in[11];
    const float* g2       = (const float*)d_in[12];
    const float* b2       = (const float*)d_in[13];
    float* out = (float*)d_out;

    float *t1, *t3, *sumb, *sum2b;
    __nv_bfloat16 *y0h, *y0l, *t2h, *t2l;
    cudaGetSymbolAddress((void**)&t1, g_t1);
    cudaGetSymbolAddress((void**)&t3, g_t3);
    cudaGetSymbolAddress((void**)&y0h, g_y0h);
    cudaGetSymbolAddress((void**)&y0l, g_y0l);
    cudaGetSymbolAddress((void**)&t2h, g_t2h);
    cudaGetSymbolAddress((void**)&t2l, g_t2l);
    cudaGetSymbolAddress((void**)&sumb, g_sum);
    cudaGetSymbolAddress((void**)&sum2b, g_sum2);
    float* s0  = sumb;            float* q0 = sum2b;
    float* s1  = sumb + COUT;     float* q1 = sum2b + COUT;
    float* s2  = sumb + 2*COUT;   float* q2 = sum2b + 2*COUT;

    init_kernel<<<1, 128>>>();
    tab_kernel<<<(HW + 255) / 256, 256>>>(x_range);
    gather_kernel<<<dim3(HW / 64, CIN / 64), 256>>>(x, range_o);

    gemm_kernel<<<dim3(HW / 64, COUT / 64), 256>>>(w_reduce, y0h, y0l, t1, CIN, s0, q0);
    dw_kernel<<<dim3(HW / 4 / 256, COUT), 256>>>(t1, dw1, t2h, t2l, s0, q0, g_r, b_r);

    gemm_kernel<<<dim3(HW / 64, COUT / 64), 256>>>(pw1, t2h, t2l, t3, COUT, s1, q1);
    dw_kernel<<<dim3(HW / 4 / 256, COUT), 256>>>(t3, dw2, t2h, t2l, s1, q1, g1, b1);

    gemm_kernel<<<dim3(HW / 64, COUT / 64), 256>>>(pw2, t2h, t2l, t1, COUT, s2, q2);
    apply_kernel<<<(COUT * HW / 4 + 255) / 256, 256>>>(t1, out, s2, q2, g2, b2);
}

// round 9
// speedup vs baseline: 1.6255x; 1.0371x over previous
#include <cuda_runtime.h>
#include <cuda_bf16.h>
#include <math.h>
#include <stdint.h>

// Problem constants
#define CIN   256
#define COUT  128
#define Hh    64
#define Ww    192
#define HW    (Hh*Ww)          // 12288
#define Hp    (Hh+2)           // 66
#define Wp    (Ww+2)           // 194
#define Pp    (Hp*Wp)          // 12804
#define EPSv  1e-5f
#define LEAK  0.01f

// ---------------- scratch (static __device__ — no allocation) ----------------
__device__ int   g_tbase[9 * HW];
__device__ float g_tw3[27 * HW];
__device__ __nv_bfloat16 g_y0h[CIN * HW];   // gather output, bf16 hi plane
__device__ __nv_bfloat16 g_y0l[CIN * HW];   // gather output, bf16 lo plane
__device__ float g_t1[COUT * HW];           // GEMM fp32 outputs
__device__ float g_t3[COUT * HW];
__device__ __nv_bfloat16 g_t2h[COUT * HW];  // dw output hi/lo planes
__device__ __nv_bfloat16 g_t2l[COUT * HW];
__device__ float g_sum[3][COUT];
__device__ float g_sum2[3][COUT];

__device__ __forceinline__ void split_bf16(float v, __nv_bfloat16& h, __nv_bfloat16& l) {
    h = __float2bfloat16(v);
    l = __float2bfloat16(v - __bfloat162float(h));
}

// ---------------- 0) zero the stat accumulators ----------------
__global__ void init_kernel() {
    int i = threadIdx.x;
    if (i < COUT) {
        #pragma unroll
        for (int s = 0; s < 3; s++) { g_sum[s][i] = 0.f; g_sum2[s][i] = 0.f; }
    }
}

// ---------------- 1) per-pixel gather tables (window-compressed) ----------------
__global__ void tab_kernel(const float* __restrict__ xr) {
    int p = blockIdx.x * 256 + threadIdx.x;
    if (p >= HW) return;
    float off = 3.0f * (1.0f / (1.0f + expf(-xr[p])));
    int r = p / Ww, cc = p - r * Ww;
    float v0 = (float)((r + 1) * Wp + (cc + 1));
    const float xo9[9] = {-1,0,1,-1,0,1,-1,0,1};
    const float yo9[9] = {-1,-1,-1,0,0,0,1,1,1};
    const float Pm1 = (float)(Pp - 1);
    const float Wpf = (float)Wp;
    #pragma unroll
    for (int k = 0; k < 9; k++) {
        float xo = xo9[k], yo = yo9[k];
        float pre  = v0 + xo + yo * Wpf;
        float offv = __fadd_rn(__fmul_rn(off, xo), yo * Wpf);
        float after = __fadd_rn(pre, offv);
        float avf  = fminf(fmaxf(pre + floorf(offv), 0.f), Pm1);
        float avf1 = fminf(fmaxf(avf + xo, 0.f), Pm1);
        float avc  = fminf(fmaxf(pre + ceilf(offv), 0.f), Pm1);
        float avc1 = fminf(fmaxf(avc + xo, 0.f), Pm1);
        float g1w = fabsf((after - avf)  / Wpf);
        float g2w = fabsf((avc1 - after) / Wpf);
        float wq[4];
        wq[0] = g1w * fabsf(after - avf);
        wq[1] = g1w * fabsf(avf1 - after);
        wq[2] = g2w * fabsf(after - avc1);
        wq[3] = g2w * fabsf(avc  - after);
        int iq[4] = {(int)avf, (int)avf1, (int)avc1, (int)avc};
        int lo = min(min(iq[0], iq[1]), min(iq[2], iq[3]));
        float w3[3] = {0.f, 0.f, 0.f};
        #pragma unroll
        for (int j = 0; j < 4; j++) w3[iq[j] - lo] += wq[j];
        int vbase = -1, firstslot = 0;
        #pragma unroll
        for (int s = 0; s < 3; s++) {
            int id = lo + s;
            int rr = id / Wp, c2 = id - rr * Wp;
            bool valid = (rr >= 1 && rr <= Hh && c2 >= 1 && c2 <= Ww);
            if (!valid) w3[s] = 0.f;
            else if (w3[s] != 0.f && vbase < 0) {
                vbase = (rr - 1) * Ww + (c2 - 1);
                firstslot = s;
            }
        }
        float fw[3] = {0.f, 0.f, 0.f};
        int bidx = 0;
        if (vbase >= 0) {
            int base = vbase - firstslot;
            bidx = min(max(base, 0), HW - 3);
            #pragma unroll
            for (int s = 0; s < 3; s++)
                if (w3[s] != 0.f) fw[(base + s) - bidx] += w3[s];
        }
        g_tbase[k * HW + p] = bidx;
        g_tw3[(k * 3 + 0) * HW + p] = fw[0];
        g_tw3[(k * 3 + 1) * HW + p] = fw[1];
        g_tw3[(k * 3 + 2) * HW + p] = fw[2];
    }
}

// ---------------- 2) deformable gather-contraction (taps-outer) ----------------
__global__ void gather_kernel(const float* __restrict__ x,
                              const float* __restrict__ ro /* (CIN,9) */) {
    __shared__ int   s_base[9 * 64];
    __shared__ float s_w[27 * 64];
    __shared__ __align__(16) float s_ro[9 * 64];
    int p0 = blockIdx.x * 64;
    int c0 = blockIdx.y * 64;
    int tid = threadIdx.x;
    for (int i = tid; i < 9 * 64; i += 256) {
        int t = i >> 6, px = i & 63;
        s_base[i] = g_tbase[t * HW + p0 + px];
    }
    for (int i = tid; i < 27 * 64; i += 256) {
        int t = i >> 6, px = i & 63;
        s_w[i] = g_tw3[t * HW + p0 + px];
    }
    for (int i = tid; i < 9 * 64; i += 256) {
        int k = i >> 6, cl = i & 63;
        s_ro[i] = ro[(c0 + cl) * 9 + k];
    }
    __syncthreads();
    int px = tid & 63;
    int cg = tid >> 6;
    int p = p0 + px;
    int cbase = c0 + cg * 16;
    const float* xc = x + (size_t)cbase * HW;

    float acc[16];
    #pragma unroll
    for (int i = 0; i < 16; i++) acc[i] = 0.f;

    #pragma unroll
    for (int k = 0; k < 9; k++) {
        int   b  = s_base[k * 64 + px];
        float w0 = s_w[(k * 3 + 0) * 64 + px];
        float w1 = s_w[(k * 3 + 1) * 64 + px];
        float w2 = s_w[(k * 3 + 2) * 64 + px];
        float4 r0 = *(const float4*)&s_ro[k * 64 + cg * 16 + 0];
        float4 r1 = *(const float4*)&s_ro[k * 64 + cg * 16 + 4];
        float4 r2 = *(const float4*)&s_ro[k * 64 + cg * 16 + 8];
        float4 r3 = *(const float4*)&s_ro[k * 64 + cg * 16 + 12];
        float rk[16] = {r0.x, r0.y, r0.z, r0.w, r1.x, r1.y, r1.z, r1.w,
                        r2.x, r2.y, r2.z, r2.w, r3.x, r3.y, r3.z, r3.w};
        const float* xb = xc + b;
        #pragma unroll
        for (int ci = 0; ci < 16; ci++) {
            const float* xp = xb + (size_t)ci * HW;
            float s = fmaf(w0, __ldg(xp + 0),
                      fmaf(w1, __ldg(xp + 1),
                           w2 * __ldg(xp + 2)));
            acc[ci] = fmaf(rk[ci], s, acc[ci]);
        }
    }
    #pragma unroll
    for (int ci = 0; ci < 16; ci++) {
        __nv_bfloat16 h, l;
        split_bf16(acc[ci], h, l);
        size_t o = (size_t)(cbase + ci) * HW + p;
        g_y0h[o] = h;
        g_y0l[o] = l;
    }
}

// ---------------- 3) bf16 split-precision tensor-core GEMM + BN-stat epilogue ----
// C[M=128,N=HW] = A[fp32] * B[bf16 hi/lo planes].
// CTA tile 64x64, K-chunk 16, 8 warps (warp tile 32x16), mma.sync m16n8k16.
// Double-buffered smem, register prefetch, ONE sync per stage.
__device__ __forceinline__ void mma_bf16(float d[4], const uint32_t a[4], const uint32_t b[2]) {
    asm volatile(
        "mma.sync.aligned.m16n8k16.row.col.f32.bf16.bf16.f32 "
        "{%0,%1,%2,%3}, {%4,%5,%6,%7}, {%8,%9}, {%10,%11,%12,%13};"
        : "=f"(d[0]), "=f"(d[1]), "=f"(d[2]), "=f"(d[3])
        : "r"(a[0]), "r"(a[1]), "r"(a[2]), "r"(a[3]),
          "r"(b[0]), "r"(b[1]),
          "f"(d[0]), "f"(d[1]), "f"(d[2]), "f"(d[3]));
}

__global__ void __launch_bounds__(256)
gemm_kernel(const float* __restrict__ A,
            const __nv_bfloat16* __restrict__ Bh,
            const __nv_bfloat16* __restrict__ Bl,
            float* __restrict__ C, int K,
            float* __restrict__ sum, float* __restrict__ sum2) {
    // smem tiles: rows padded to 9 uint32 (18 bf16) -> conflict-free frag reads
    __shared__ uint32_t Ah[2][64][9], Al[2][64][9];   // [buf][m][k/2]
    __shared__ uint32_t Bhs[2][64][9], Bls[2][64][9]; // [buf][n][k/2]
    const int N = HW;
    int bn = blockIdx.x * 64, bm = blockIdx.y * 64;
    int tid = threadIdx.x;
    int lane = tid & 31;
    int warp = tid >> 5;
    int g = lane >> 2, t = lane & 3;           // mma group/thread ids
    int m0 = (warp & 1) * 32;                  // warp m offset in tile
    int n0 = (warp >> 1) * 16;                 // warp n offset in tile

    // staging indices
    int ar = tid >> 2, akq = tid & 3;          // A: row, k-quad (4 floats)
    int bkr = tid >> 4, bn0 = (tid & 15) * 4;  // B: k row, 4 n values

    const float* ApBase = &A[(size_t)(bm + ar) * K + akq * 4];
    const __nv_bfloat16* BhBase = &Bh[(size_t)bkr * N + bn + bn0];
    const __nv_bfloat16* BlBase = &Bl[(size_t)bkr * N + bn + bn0];

    float d[2][2][4];
    #pragma unroll
    for (int i = 0; i < 2; i++)
        #pragma unroll
        for (int j = 0; j < 2; j++)
            #pragma unroll
            for (int q = 0; q < 4; q++) d[i][j][q] = 0.f;

    // ---- stage helpers (macro-free inline pattern) ----
    float4 av = *(const float4*)ApBase;
    uint2  vh = *(const uint2*)BhBase;
    uint2  vl = *(const uint2*)BlBase;

    // store stage 0
    {
        __nv_bfloat16 h0, l0, h1, l1, h2, l2, h3, l3;
        split_bf16(av.x, h0, l0); split_bf16(av.y, h1, l1);
        split_bf16(av.z, h2, l2); split_bf16(av.w, h3, l3);
        __nv_bfloat162 hp0 = {h0, h1}, hp1 = {h2, h3};
        __nv_bfloat162 lp0 = {l0, l1}, lp1 = {l2, l3};
        Ah[0][ar][akq * 2 + 0] = *(uint32_t*)&hp0;
        Ah[0][ar][akq * 2 + 1] = *(uint32_t*)&hp1;
        Al[0][ar][akq * 2 + 0] = *(uint32_t*)&lp0;
        Al[0][ar][akq * 2 + 1] = *(uint32_t*)&lp1;
        __nv_bfloat16* bh16 = (__nv_bfloat16*)&vh;
        __nv_bfloat16* bl16 = (__nv_bfloat16*)&vl;
        #pragma unroll
        for (int j = 0; j < 4; j++) {
            ((__nv_bfloat16*)&Bhs[0][bn0 + j][0])[bkr] = bh16[j];
            ((__nv_bfloat16*)&Bls[0][bn0 + j][0])[bkr] = bl16[j];
        }
    }
    __syncthreads();

    int nstage = K / 16;
    for (int s = 0; s < nstage; s++) {
        int buf = s & 1;
        bool more = (s + 1 < nstage);
        if (more) {                            // prefetch next stage into registers
            int k0 = (s + 1) * 16;
            av = *(const float4*)(ApBase + k0);
            vh = *(const uint2*)(BhBase + (size_t)k0 * N);
            vl = *(const uint2*)(BlBase + (size_t)k0 * N);
        }

        // --- fragments + mma on current buffer ---
        uint32_t ah[2][4], al[2][4], bh[2][2], bl[2][2];
        #pragma unroll
        for (int mt = 0; mt < 2; mt++) {
            int r0 = m0 + mt * 16 + g;
            ah[mt][0] = Ah[buf][r0][t];     ah[mt][1] = Ah[buf][r0 + 8][t];
            ah[mt][2] = Ah[buf][r0][t + 4]; ah[mt][3] = Ah[buf][r0 + 8][t + 4];
            al[mt][0] = Al[buf][r0][t];     al[mt][1] = Al[buf][r0 + 8][t];
            al[mt][2] = Al[buf][r0][t + 4]; al[mt][3] = Al[buf][r0 + 8][t + 4];
        }
        #pragma unroll
        for (int nt = 0; nt < 2; nt++) {
            int n = n0 + nt * 8 + g;
            bh[nt][0] = Bhs[buf][n][t]; bh[nt][1] = Bhs[buf][n][t + 4];
            bl[nt][0] = Bls[buf][n][t]; bl[nt][1] = Bls[buf][n][t + 4];
        }
        #pragma unroll
        for (int mt = 0; mt < 2; mt++)
            #pragma unroll
            for (int nt = 0; nt < 2; nt++) {
                mma_bf16(d[mt][nt], ah[mt], bh[nt]);
                mma_bf16(d[mt][nt], ah[mt], bl[nt]);
                mma_bf16(d[mt][nt], al[mt], bh[nt]);
            }

        if (more) {                            // store prefetched stage, single sync
            int nb = buf ^ 1;
            __nv_bfloat16 h0, l0, h1, l1, h2, l2, h3, l3;
            split_bf16(av.x, h0, l0); split_bf16(av.y, h1, l1);
            split_bf16(av.z, h2, l2); split_bf16(av.w, h3, l3);
            __nv_bfloat162 hp0 = {h0, h1}, hp1 = {h2, h3};
            __nv_bfloat162 lp0 = {l0, l1}, lp1 = {l2, l3};
            Ah[nb][ar][akq * 2 + 0] = *(uint32_t*)&hp0;
            Ah[nb][ar][akq * 2 + 1] = *(uint32_t*)&hp1;
            Al[nb][ar][akq * 2 + 0] = *(uint32_t*)&lp0;
            Al[nb][ar][akq * 2 + 1] = *(uint32_t*)&lp1;
            __nv_bfloat16* bh16 = (__nv_bfloat16*)&vh;
            __nv_bfloat16* bl16 = (__nv_bfloat16*)&vl;
            #pragma unroll
            for (int j = 0; j < 4; j++) {
                ((__nv_bfloat16*)&Bhs[nb][bn0 + j][0])[bkr] = bh16[j];
                ((__nv_bfloat16*)&Bls[nb][bn0 + j][0])[bkr] = bl16[j];
            }
            __syncthreads();
        }
    }

    // --- write C + fused BN stats ---
    float srow[2][2] = {{0.f, 0.f}, {0.f, 0.f}};
    float qrow[2][2] = {{0.f, 0.f}, {0.f, 0.f}};
    #pragma unroll
    for (int mt = 0; mt < 2; mt++) {
        int r0 = bm + m0 + mt * 16 + g;
        #pragma unroll
        for (int nt = 0; nt < 2; nt++) {
            int col = bn + n0 + nt * 8 + 2 * t;
            float2 v0 = make_float2(d[mt][nt][0], d[mt][nt][1]);
            float2 v1 = make_float2(d[mt][nt][2], d[mt][nt][3]);
            *(float2*)&C[(size_t)r0 * N + col] = v0;
            *(float2*)&C[(size_t)(r0 + 8) * N + col] = v1;
            srow[mt][0] += v0.x + v0.y;
            srow[mt][1] += v1.x + v1.y;
            qrow[mt][0] = fmaf(v0.x, v0.x, fmaf(v0.y, v0.y, qrow[mt][0]));
            qrow[mt][1] = fmaf(v1.x, v1.x, fmaf(v1.y, v1.y, qrow[mt][1]));
        }
    }
    #pragma unroll
    for (int mt = 0; mt < 2; mt++)
        #pragma unroll
        for (int h = 0; h < 2; h++) {
            float s = srow[mt][h], q = qrow[mt][h];
            s += __shfl_down_sync(0xffffffffu, s, 1, 4);
            s += __shfl_down_sync(0xffffffffu, s, 2, 4);
            q += __shfl_down_sync(0xffffffffu, q, 1, 4);
            q += __shfl_down_sync(0xffffffffu, q, 2, 4);
            if (t == 0) {
                int row = bm + m0 + mt * 16 + g + h * 8;
                atomicAdd(&sum[row], s);
                atomicAdd(&sum2[row], q);
            }
        }
}

// ---------------- BN scale/bias from accumulated stats ----------------
__device__ __forceinline__ void bn_coeffs(int c, const float* sum, const float* sum2,
                                          const float* __restrict__ g,
                                          const float* __restrict__ b,
                                          float& sc, float& bi) {
    float mean = sum[c] * (1.f / (float)HW);
    float var  = sum2[c] * (1.f / (float)HW) - mean * mean;
    float rstd = rsqrtf(var + EPSv);
    sc = g[c] * rstd;
    bi = b[c] - mean * sc;
}

__device__ __forceinline__ float bn_leaky(float v, float sc, float bi) {
    float y = fmaf(v, sc, bi);
    return y >= 0.f ? y : LEAK * y;
}

// ---------------- 4) depthwise 3x3, 4 px/thread, fused BN+leaky, bf16-split out ----
__global__ void dw_kernel(const float* __restrict__ in, const float* __restrict__ dw,
                          __nv_bfloat16* __restrict__ outh, __nv_bfloat16* __restrict__ outl,
                          const float* __restrict__ sum, const float* __restrict__ sum2,
                          const float* __restrict__ g, const float* __restrict__ b) {
    int c = blockIdx.y;
    int q = blockIdx.x * 256 + threadIdx.x;
    if (q >= HW / 4) return;
    int p0 = q * 4;
    int r = p0 / Ww, col0 = p0 - r * Ww;
    float sc, bi;
    bn_coeffs(c, sum, sum2, g, b, sc, bi);
    float wl[9];
    #pragma unroll
    for (int i = 0; i < 9; i++) wl[i] = dw[c * 9 + i];
    const float* ip = in + (size_t)c * HW;
    float vin[3][6];
    #pragma unroll
    for (int tr = 0; tr < 3; tr++) {
        int rr = r + tr - 1;
        bool rowok = (rr >= 0 && rr < Hh);
        #pragma unroll
        for (int j = 0; j < 6; j++) {
            int cc = col0 - 1 + j;
            float v = 0.f;
            if (rowok && cc >= 0 && cc < Ww)
                v = bn_leaky(ip[rr * Ww + cc], sc, bi);
            vin[tr][j] = v;
        }
    }
    __nv_bfloat16 oh[4], ol[4];
    #pragma unroll
    for (int i = 0; i < 4; i++) {
        float acc = 0.f;
        #pragma unroll
        for (int tr = 0; tr < 3; tr++)
            #pragma unroll
            for (int dx = 0; dx < 3; dx++)
                acc = fmaf(vin[tr][i + dx], wl[tr * 3 + dx], acc);
        split_bf16(acc, oh[i], ol[i]);
    }
    *(uint2*)&outh[(size_t)c * HW + p0] = *(uint2*)oh;
    *(uint2*)&outl[(size_t)c * HW + p0] = *(uint2*)ol;
}

// ---------------- 5) final BN+leaky apply (vectorized) ----------------
__global__ void apply_kernel(const float* __restrict__ in, float* __restrict__ out,
                             const float* __restrict__ sum, const float* __restrict__ sum2,
                             const float* __restrict__ g, const float* __restrict__ b) {
    int i = blockIdx.x * 256 + threadIdx.x;
    if (i >= COUT * HW / 4) return;
    int c = (i * 4) / HW;
    float sc, bi;
    bn_coeffs(c, sum, sum2, g, b, sc, bi);
    float4 v = ((const float4*)in)[i];
    v.x = bn_leaky(v.x, sc, bi);
    v.y = bn_leaky(v.y, sc, bi);
    v.z = bn_leaky(v.z, sc, bi);
    v.w = bn_leaky(v.w, sc, bi);
    ((float4*)out)[i] = v;
}

// ---------------- launch ----------------
extern "C" void kernel_launch(void* const* d_in, const int* in_sizes, int n_in,
                              void* d_out, int out_size) {
    const float* x        = (const float*)d_in[0];
    const float* x_range  = (const float*)d_in[1];
    const float* range_o  = (const float*)d_in[2];
    const float* w_reduce = (const float*)d_in[3];
    const float* g_r      = (const float*)d_in[4];
    const float* b_r      = (const float*)d_in[5];
    const float* dw1      = (const float*)d_in[6];
    const float* pw1      = (const float*)d_in[7];
    const float* g1       = (const float*)d_in[8];
    const float* b1       = (const float*)d_in[9];
    const float* dw2      = (const float*)d_in[10];
    const float* pw2      = (const float*)d_in[11];
    const float* g2       = (const float*)d_in[12];
    const float* b2       = (const float*)d_in[13];
    float* out = (float*)d_out;

    float *t1, *t3, *sumb, *sum2b;
    __nv_bfloat16 *y0h, *y0l, *t2h, *t2l;
    cudaGetSymbolAddress((void**)&t1, g_t1);
    cudaGetSymbolAddress((void**)&t3, g_t3);
    cudaGetSymbolAddress((void**)&y0h, g_y0h);
    cudaGetSymbolAddress((void**)&y0l, g_y0l);
    cudaGetSymbolAddress((void**)&t2h, g_t2h);
    cudaGetSymbolAddress((void**)&t2l, g_t2l);
    cudaGetSymbolAddress((void**)&sumb, g_sum);
    cudaGetSymbolAddress((void**)&sum2b, g_sum2);
    float* s0  = sumb;            float* q0 = sum2b;
    float* s1  = sumb + COUT;     float* q1 = sum2b + COUT;
    float* s2  = sumb + 2*COUT;   float* q2 = sum2b + 2*COUT;

    init_kernel<<<1, 128>>>();
    tab_kernel<<<(HW + 255) / 256, 256>>>(x_range);
    gather_kernel<<<dim3(HW / 64, CIN / 64), 256>>>(x, range_o);

    gemm_kernel<<<dim3(HW / 64, COUT / 64), 256>>>(w_reduce, y0h, y0l, t1, CIN, s0, q0);
    dw_kernel<<<dim3(HW / 4 / 256, COUT), 256>>>(t1, dw1, t2h, t2l, s0, q0, g_r, b_r);

    gemm_kernel<<<dim3(HW / 64, COUT / 64), 256>>>(pw1, t2h, t2l, t3, COUT, s1, q1);
    dw_kernel<<<dim3(HW / 4 / 256, COUT), 256>>>(t3, dw2, t2h, t2l, s1, q1, g1, b1);

    gemm_kernel<<<dim3(HW / 64, COUT / 64), 256>>>(pw2, t2h, t2l, t1, COUT, s2, q2);
    apply_kernel<<<(COUT * HW / 4 + 255) / 256, 256>>>(t1, out, s2, q2, g2, b2);
}

// round 10
// speedup vs baseline: 1.8491x; 1.1375x over previous
#include <cuda_runtime.h>
#include <cuda_bf16.h>
#include <math.h>
#include <stdint.h>

// Problem constants
#define CIN   256
#define COUT  128
#define Hh    64
#define Ww    192
#define HW    (Hh*Ww)          // 12288
#define Hp    (Hh+2)           // 66
#define Wp    (Ww+2)           // 194
#define Pp    (Hp*Wp)          // 12804
#define EPSv  1e-5f
#define LEAK  0.01f

// ---------------- scratch (static __device__ — no allocation) ----------------
__device__ int   g_tbase[9 * HW];
__device__ float g_tw3[27 * HW];
__device__ __nv_bfloat16 g_y0h[CIN * HW];   // gather output, bf16 hi plane
__device__ __nv_bfloat16 g_y0l[CIN * HW];   // gather output, bf16 lo plane
__device__ float g_t1[COUT * HW];           // GEMM fp32 outputs
__device__ float g_t3[COUT * HW];
__device__ __nv_bfloat16 g_t2h[COUT * HW];  // dw output hi/lo planes
__device__ __nv_bfloat16 g_t2l[COUT * HW];
__device__ __nv_bfloat16 g_wh[COUT * (CIN + COUT + COUT)];  // pre-split weights hi
__device__ __nv_bfloat16 g_wl[COUT * (CIN + COUT + COUT)];  // pre-split weights lo
__device__ float g_sum[3][COUT];
__device__ float g_sum2[3][COUT];

__device__ __forceinline__ void split_bf16(float v, __nv_bfloat16& h, __nv_bfloat16& l) {
    h = __float2bfloat16(v);
    l = __float2bfloat16(v - __bfloat162float(h));
}

// ---------------- 0) zero stats ----------------
__global__ void init_kernel() {
    int i = threadIdx.x;
    if (i < COUT) {
        #pragma unroll
        for (int s = 0; s < 3; s++) { g_sum[s][i] = 0.f; g_sum2[s][i] = 0.f; }
    }
}

// ---------------- 0b) pre-split weights to bf16 hi/lo ----------------
__global__ void wsplit_kernel(const float* __restrict__ w0,
                              const float* __restrict__ w1,
                              const float* __restrict__ w2) {
    int i = blockIdx.x * 256 + threadIdx.x;   // total 65536
    const int n0 = COUT * CIN;                // 32768
    const int n1 = COUT * COUT;               // 16384
    float v;
    if (i < n0)                 v = w0[i];
    else if (i < n0 + n1)       v = w1[i - n0];
    else if (i < n0 + 2 * n1)   v = w2[i - n0 - n1];
    else return;
    __nv_bfloat16 h, l;
    split_bf16(v, h, l);
    g_wh[i] = h;
    g_wl[i] = l;
}

// ---------------- 1) per-pixel gather tables (window-compressed) ----------------
__global__ void tab_kernel(const float* __restrict__ xr) {
    int p = blockIdx.x * 256 + threadIdx.x;
    if (p >= HW) return;
    float off = 3.0f * (1.0f / (1.0f + expf(-xr[p])));
    int r = p / Ww, cc = p - r * Ww;
    float v0 = (float)((r + 1) * Wp + (cc + 1));
    const float xo9[9] = {-1,0,1,-1,0,1,-1,0,1};
    const float yo9[9] = {-1,-1,-1,0,0,0,1,1,1};
    const float Pm1 = (float)(Pp - 1);
    const float Wpf = (float)Wp;
    #pragma unroll
    for (int k = 0; k < 9; k++) {
        float xo = xo9[k], yo = yo9[k];
        float pre  = v0 + xo + yo * Wpf;
        float offv = __fadd_rn(__fmul_rn(off, xo), yo * Wpf);
        float after = __fadd_rn(pre, offv);
        float avf  = fminf(fmaxf(pre + floorf(offv), 0.f), Pm1);
        float avf1 = fminf(fmaxf(avf + xo, 0.f), Pm1);
        float avc  = fminf(fmaxf(pre + ceilf(offv), 0.f), Pm1);
        float avc1 = fminf(fmaxf(avc + xo, 0.f), Pm1);
        float g1w = fabsf((after - avf)  / Wpf);
        float g2w = fabsf((avc1 - after) / Wpf);
        float wq[4];
        wq[0] = g1w * fabsf(after - avf);
        wq[1] = g1w * fabsf(avf1 - after);
        wq[2] = g2w * fabsf(after - avc1);
        wq[3] = g2w * fabsf(avc  - after);
        int iq[4] = {(int)avf, (int)avf1, (int)avc1, (int)avc};
        int lo = min(min(iq[0], iq[1]), min(iq[2], iq[3]));
        float w3[3] = {0.f, 0.f, 0.f};
        #pragma unroll
        for (int j = 0; j < 4; j++) w3[iq[j] - lo] += wq[j];
        int vbase = -1, firstslot = 0;
        #pragma unroll
        for (int s = 0; s < 3; s++) {
            int id = lo + s;
            int rr = id / Wp, c2 = id - rr * Wp;
            bool valid = (rr >= 1 && rr <= Hh && c2 >= 1 && c2 <= Ww);
            if (!valid) w3[s] = 0.f;
            else if (w3[s] != 0.f && vbase < 0) {
                vbase = (rr - 1) * Ww + (c2 - 1);
                firstslot = s;
            }
        }
        float fw[3] = {0.f, 0.f, 0.f};
        int bidx = 0;
        if (vbase >= 0) {
            int base = vbase - firstslot;
            bidx = min(max(base, 0), HW - 3);
            #pragma unroll
            for (int s = 0; s < 3; s++)
                if (w3[s] != 0.f) fw[(base + s) - bidx] += w3[s];
        }
        g_tbase[k * HW + p] = bidx;
        g_tw3[(k * 3 + 0) * HW + p] = fw[0];
        g_tw3[(k * 3 + 1) * HW + p] = fw[1];
        g_tw3[(k * 3 + 2) * HW + p] = fw[2];
    }
}

// ---------------- 2) deformable gather-contraction (taps-outer) ----------------
__global__ void gather_kernel(const float* __restrict__ x,
                              const float* __restrict__ ro /* (CIN,9) */) {
    __shared__ int   s_base[9 * 64];
    __shared__ float s_w[27 * 64];
    __shared__ __align__(16) float s_ro[9 * 64];
    int p0 = blockIdx.x * 64;
    int c0 = blockIdx.y * 64;
    int tid = threadIdx.x;
    for (int i = tid; i < 9 * 64; i += 256) {
        int t = i >> 6, px = i & 63;
        s_base[i] = g_tbase[t * HW + p0 + px];
    }
    for (int i = tid; i < 27 * 64; i += 256) {
        int t = i >> 6, px = i & 63;
        s_w[i] = g_tw3[t * HW + p0 + px];
    }
    for (int i = tid; i < 9 * 64; i += 256) {
        int k = i >> 6, cl = i & 63;
        s_ro[i] = ro[(c0 + cl) * 9 + k];
    }
    __syncthreads();
    int px = tid & 63;
    int cg = tid >> 6;
    int p = p0 + px;
    int cbase = c0 + cg * 16;
    const float* xc = x + (size_t)cbase * HW;

    float acc[16];
    #pragma unroll
    for (int i = 0; i < 16; i++) acc[i] = 0.f;

    #pragma unroll
    for (int k = 0; k < 9; k++) {
        int   b  = s_base[k * 64 + px];
        float w0 = s_w[(k * 3 + 0) * 64 + px];
        float w1 = s_w[(k * 3 + 1) * 64 + px];
        float w2 = s_w[(k * 3 + 2) * 64 + px];
        float4 r0 = *(const float4*)&s_ro[k * 64 + cg * 16 + 0];
        float4 r1 = *(const float4*)&s_ro[k * 64 + cg * 16 + 4];
        float4 r2 = *(const float4*)&s_ro[k * 64 + cg * 16 + 8];
        float4 r3 = *(const float4*)&s_ro[k * 64 + cg * 16 + 12];
        float rk[16] = {r0.x, r0.y, r0.z, r0.w, r1.x, r1.y, r1.z, r1.w,
                        r2.x, r2.y, r2.z, r2.w, r3.x, r3.y, r3.z, r3.w};
        const float* xb = xc + b;
        #pragma unroll
        for (int ci = 0; ci < 16; ci++) {
            const float* xp = xb + (size_t)ci * HW;
            float s = fmaf(w0, __ldg(xp + 0),
                      fmaf(w1, __ldg(xp + 1),
                           w2 * __ldg(xp + 2)));
            acc[ci] = fmaf(rk[ci], s, acc[ci]);
        }
    }
    #pragma unroll
    for (int ci = 0; ci < 16; ci++) {
        __nv_bfloat16 h, l;
        split_bf16(acc[ci], h, l);
        size_t o = (size_t)(cbase + ci) * HW + p;
        g_y0h[o] = h;
        g_y0l[o] = l;
    }
}

// ---------------- 3) bf16 split tensor-core GEMM: cp.async + ldmatrix ----------
// C[128,N] = A[bf16 hi/lo] * B[bf16 hi/lo]. CTA tile 64x64, K-chunk 16,
// 8 warps (warp tile 32x16), 3-stage cp.async ring, ONE sync per stage.
__device__ __forceinline__ void mma_bf16(float d[4], const uint32_t a[4], const uint32_t b0, const uint32_t b1) {
    asm volatile(
        "mma.sync.aligned.m16n8k16.row.col.f32.bf16.bf16.f32 "
        "{%0,%1,%2,%3}, {%4,%5,%6,%7}, {%8,%9}, {%10,%11,%12,%13};"
        : "=f"(d[0]), "=f"(d[1]), "=f"(d[2]), "=f"(d[3])
        : "r"(a[0]), "r"(a[1]), "r"(a[2]), "r"(a[3]),
          "r"(b0), "r"(b1),
          "f"(d[0]), "f"(d[1]), "f"(d[2]), "f"(d[3]));
}

#define CP8(dst, src) \
    asm volatile("cp.async.ca.shared.global [%0], [%1], 8;" :: "r"(dst), "l"(src))
#define LDSM_X4(r0, r1, r2, r3, addr) \
    asm volatile("ldmatrix.sync.aligned.m8n8.x4.shared.b16 {%0,%1,%2,%3}, [%4];" \
                 : "=r"(r0), "=r"(r1), "=r"(r2), "=r"(r3) : "r"(addr))
#define LDSM_X4T(r0, r1, r2, r3, addr) \
    asm volatile("ldmatrix.sync.aligned.m8n8.x4.trans.shared.b16 {%0,%1,%2,%3}, [%4];" \
                 : "=r"(r0), "=r"(r1), "=r"(r2), "=r"(r3) : "r"(addr))

// per-buffer layout (bytes): Ah 0..3072, Al 3072..6144, Bh 6144..8192, Bl 8192..10240
#define BUFSZ 10240

__global__ void __launch_bounds__(256)
gemm_kernel(const __nv_bfloat16* __restrict__ Ahg,
            const __nv_bfloat16* __restrict__ Alg,
            const __nv_bfloat16* __restrict__ Bh,
            const __nv_bfloat16* __restrict__ Bl,
            float* __restrict__ C, int K,
            float* __restrict__ sum, float* __restrict__ sum2) {
    __shared__ __align__(16) char sm[3 * BUFSZ];
    const int N = HW;
    int bn = blockIdx.x * 64, bm = blockIdx.y * 64;
    int tid = threadIdx.x;
    int lane = tid & 31;
    int warp = tid >> 5;
    int g = lane >> 2, t = lane & 3;
    int m0 = (warp & 1) * 32;
    int n0 = (warp >> 1) * 16;

    uint32_t smb = (uint32_t)__cvta_generic_to_shared(sm);

    // staging indices
    int ar  = tid >> 2, akq = tid & 3;          // A: row, 8B chunk
    int bkr = tid >> 4, bn0 = (tid & 15) * 4;   // B: k row, 4 n values
    uint32_t aoffst = ar * 48 + akq * 8;
    int bu = (tid & 15) >> 1, bhalf = tid & 1;
    uint32_t boffst = bkr * 128 + (uint32_t)((bu ^ (bkr & 7)) << 4) + bhalf * 8;
    const __nv_bfloat16* ApH = Ahg + (size_t)(bm + ar) * K + akq * 4;
    const __nv_bfloat16* ApL = Alg + (size_t)(bm + ar) * K + akq * 4;
    const __nv_bfloat16* BpH = Bh + (size_t)bkr * N + bn + bn0;
    const __nv_bfloat16* BpL = Bl + (size_t)bkr * N + bn + bn0;

    // fragment lane offsets (buffer-relative)
    uint32_t aoffld[2];
    #pragma unroll
    for (int mt = 0; mt < 2; mt++)
        aoffld[mt] = (uint32_t)((m0 + mt * 16 + (lane & 15)) * 48 + ((lane >> 4) * 8) * 2);
    uint32_t boffld;
    {
        int mi = lane >> 3;
        int kk = (mi & 1) * 8 + (lane & 7);
        int u  = (n0 >> 3) + (mi >> 1);
        boffld = (uint32_t)(kk * 128 + ((u ^ (kk & 7)) << 4));
    }

    float d[2][2][4];
    #pragma unroll
    for (int i = 0; i < 2; i++)
        #pragma unroll
        for (int j = 0; j < 2; j++)
            #pragma unroll
            for (int q = 0; q < 4; q++) d[i][j][q] = 0.f;

    int nstage = K / 16;

    // ---- prologue: issue stages 0 and 1 ----
    #pragma unroll
    for (int s = 0; s < 2; s++) {
        uint32_t base = smb + s * BUFSZ;
        int k0 = s * 16;
        CP8(base + aoffst,        ApH + k0);
        CP8(base + 3072 + aoffst, ApL + k0);
        CP8(base + 6144 + boffst, BpH + (size_t)k0 * N);
        CP8(base + 8192 + boffst, BpL + (size_t)k0 * N);
        asm volatile("cp.async.commit_group;");
    }

    int bufc = 0;
    for (int s = 0; s < nstage; s++) {
        if (s + 1 < nstage) asm volatile("cp.async.wait_group 1;");
        else                asm volatile("cp.async.wait_group 0;");
        __syncthreads();

        if (s + 2 < nstage) {
            int nb = bufc + 2; if (nb >= 3) nb -= 3;
            uint32_t base = smb + nb * BUFSZ;
            int k0 = (s + 2) * 16;
            CP8(base + aoffst,        ApH + k0);
            CP8(base + 3072 + aoffst, ApL + k0);
            CP8(base + 6144 + boffst, BpH + (size_t)k0 * N);
            CP8(base + 8192 + boffst, BpL + (size_t)k0 * N);
            asm volatile("cp.async.commit_group;");
        }

        uint32_t base = smb + bufc * BUFSZ;
        uint32_t ah[2][4], al[2][4], bhf[4], blf[4];
        LDSM_X4(ah[0][0], ah[0][1], ah[0][2], ah[0][3], base + aoffld[0]);
        LDSM_X4(ah[1][0], ah[1][1], ah[1][2], ah[1][3], base + aoffld[1]);
        LDSM_X4(al[0][0], al[0][1], al[0][2], al[0][3], base + 3072 + aoffld[0]);
        LDSM_X4(al[1][0], al[1][1], al[1][2], al[1][3], base + 3072 + aoffld[1]);
        LDSM_X4T(bhf[0], bhf[1], bhf[2], bhf[3], base + 6144 + boffld);
        LDSM_X4T(blf[0], blf[1], blf[2], blf[3], base + 8192 + boffld);

        #pragma unroll
        for (int mt = 0; mt < 2; mt++)
            #pragma unroll
            for (int nt = 0; nt < 2; nt++) {
                mma_bf16(d[mt][nt], ah[mt], bhf[nt * 2], bhf[nt * 2 + 1]);
                mma_bf16(d[mt][nt], ah[mt], blf[nt * 2], blf[nt * 2 + 1]);
                mma_bf16(d[mt][nt], al[mt], bhf[nt * 2], bhf[nt * 2 + 1]);
            }

        if (++bufc == 3) bufc = 0;
    }

    // --- write C + fused BN stats ---
    float srow[2][2] = {{0.f, 0.f}, {0.f, 0.f}};
    float qrow[2][2] = {{0.f, 0.f}, {0.f, 0.f}};
    #pragma unroll
    for (int mt = 0; mt < 2; mt++) {
        int r0 = bm + m0 + mt * 16 + g;
        #pragma unroll
        for (int nt = 0; nt < 2; nt++) {
            int col = bn + n0 + nt * 8 + 2 * t;
            float2 v0 = make_float2(d[mt][nt][0], d[mt][nt][1]);
            float2 v1 = make_float2(d[mt][nt][2], d[mt][nt][3]);
            *(float2*)&C[(size_t)r0 * N + col] = v0;
            *(float2*)&C[(size_t)(r0 + 8) * N + col] = v1;
            srow[mt][0] += v0.x + v0.y;
            srow[mt][1] += v1.x + v1.y;
            qrow[mt][0] = fmaf(v0.x, v0.x, fmaf(v0.y, v0.y, qrow[mt][0]));
            qrow[mt][1] = fmaf(v1.x, v1.x, fmaf(v1.y, v1.y, qrow[mt][1]));
        }
    }
    #pragma unroll
    for (int mt = 0; mt < 2; mt++)
        #pragma unroll
        for (int h = 0; h < 2; h++) {
            float s = srow[mt][h], q = qrow[mt][h];
            s += __shfl_down_sync(0xffffffffu, s, 1, 4);
            s += __shfl_down_sync(0xffffffffu, s, 2, 4);
            q += __shfl_down_sync(0xffffffffu, q, 1, 4);
            q += __shfl_down_sync(0xffffffffu, q, 2, 4);
            if (t == 0) {
                int row = bm + m0 + mt * 16 + g + h * 8;
                atomicAdd(&sum[row], s);
                atomicAdd(&sum2[row], q);
            }
        }
}

// ---------------- BN scale/bias from accumulated stats ----------------
__device__ __forceinline__ void bn_coeffs(int c, const float* sum, const float* sum2,
                                          const float* __restrict__ g,
                                          const float* __restrict__ b,
                                          float& sc, float& bi) {
    float mean = sum[c] * (1.f / (float)HW);
    float var  = sum2[c] * (1.f / (float)HW) - mean * mean;
    float rstd = rsqrtf(var + EPSv);
    sc = g[c] * rstd;
    bi = b[c] - mean * sc;
}

__device__ __forceinline__ float bn_leaky(float v, float sc, float bi) {
    float y = fmaf(v, sc, bi);
    return y >= 0.f ? y : LEAK * y;
}

// ---------------- 4) depthwise 3x3, 4 px/thread, fused BN+leaky, bf16-split out ----
__global__ void dw_kernel(const float* __restrict__ in, const float* __restrict__ dw,
                          __nv_bfloat16* __restrict__ outh, __nv_bfloat16* __restrict__ outl,
                          const float* __restrict__ sum, const float* __restrict__ sum2,
                          const float* __restrict__ g, const float* __restrict__ b) {
    int c = blockIdx.y;
    int q = blockIdx.x * 256 + threadIdx.x;
    if (q >= HW / 4) return;
    int p0 = q * 4;
    int r = p0 / Ww, col0 = p0 - r * Ww;
    float sc, bi;
    bn_coeffs(c, sum, sum2, g, b, sc, bi);
    float wl[9];
    #pragma unroll
    for (int i = 0; i < 9; i++) wl[i] = dw[c * 9 + i];
    const float* ip = in + (size_t)c * HW;
    float vin[3][6];
    #pragma unroll
    for (int tr = 0; tr < 3; tr++) {
        int rr = r + tr - 1;
        bool rowok = (rr >= 0 && rr < Hh);
        #pragma unroll
        for (int j = 0; j < 6; j++) {
            int cc = col0 - 1 + j;
            float v = 0.f;
            if (rowok && cc >= 0 && cc < Ww)
                v = bn_leaky(ip[rr * Ww + cc], sc, bi);
            vin[tr][j] = v;
        }
    }
    __nv_bfloat16 oh[4], ol[4];
    #pragma unroll
    for (int i = 0; i < 4; i++) {
        float acc = 0.f;
        #pragma unroll
        for (int tr = 0; tr < 3; tr++)
            #pragma unroll
            for (int dx = 0; dx < 3; dx++)
                acc = fmaf(vin[tr][i + dx], wl[tr * 3 + dx], acc);
        split_bf16(acc, oh[i], ol[i]);
    }
    *(uint2*)&outh[(size_t)c * HW + p0] = *(uint2*)oh;
    *(uint2*)&outl[(size_t)c * HW + p0] = *(uint2*)ol;
}

// ---------------- 5) final BN+leaky apply (vectorized) ----------------
__global__ void apply_kernel(const float* __restrict__ in, float* __restrict__ out,
                             const float* __restrict__ sum, const float* __restrict__ sum2,
                             const float* __restrict__ g, const float* __restrict__ b) {
    int i = blockIdx.x * 256 + threadIdx.x;
    if (i >= COUT * HW / 4) return;
    int c = (i * 4) / HW;
    float sc, bi;
    bn_coeffs(c, sum, sum2, g, b, sc, bi);
    float4 v = ((const float4*)in)[i];
    v.x = bn_leaky(v.x, sc, bi);
    v.y = bn_leaky(v.y, sc, bi);
    v.z = bn_leaky(v.z, sc, bi);
    v.w = bn_leaky(v.w, sc, bi);
    ((float4*)out)[i] = v;
}

// ---------------- launch ----------------
extern "C" void kernel_launch(void* const* d_in, const int* in_sizes, int n_in,
                              void* d_out, int out_size) {
    const float* x        = (const float*)d_in[0];
    const float* x_range  = (const float*)d_in[1];
    const float* range_o  = (const float*)d_in[2];
    const float* w_reduce = (const float*)d_in[3];
    const float* g_r      = (const float*)d_in[4];
    const float* b_r      = (const float*)d_in[5];
    const float* dw1      = (const float*)d_in[6];
    const float* pw1      = (const float*)d_in[7];
    const float* g1       = (const float*)d_in[8];
    const float* b1       = (const float*)d_in[9];
    const float* dw2      = (const float*)d_in[10];
    const float* pw2      = (const float*)d_in[11];
    const float* g2       = (const float*)d_in[12];
    const float* b2       = (const float*)d_in[13];
    float* out = (float*)d_out;

    float *t1, *t3, *sumb, *sum2b;
    __nv_bfloat16 *y0h, *y0l, *t2h, *t2l, *wh, *wlp;
    cudaGetSymbolAddress((void**)&t1, g_t1);
    cudaGetSymbolAddress((void**)&t3, g_t3);
    cudaGetSymbolAddress((void**)&y0h, g_y0h);
    cudaGetSymbolAddress((void**)&y0l, g_y0l);
    cudaGetSymbolAddress((void**)&t2h, g_t2h);
    cudaGetSymbolAddress((void**)&t2l, g_t2l);
    cudaGetSymbolAddress((void**)&wh, g_wh);
    cudaGetSymbolAddress((void**)&wlp, g_wl);
    cudaGetSymbolAddress((void**)&sumb, g_sum);
    cudaGetSymbolAddress((void**)&sum2b, g_sum2);
    float* s0  = sumb;            float* q0 = sum2b;
    float* s1  = sumb + COUT;     float* q1 = sum2b + COUT;
    float* s2  = sumb + 2*COUT;   float* q2 = sum2b + 2*COUT;
    const int W0 = COUT * CIN;          // 32768
    const int W1 = COUT * COUT;         // 16384

    init_kernel<<<1, 128>>>();
    wsplit_kernel<<<(W0 + 2 * W1) / 256, 256>>>(w_reduce, pw1, pw2);
    tab_kernel<<<(HW + 255) / 256, 256>>>(x_range);
    gather_kernel<<<dim3(HW / 64, CIN / 64), 256>>>(x, range_o);

    gemm_kernel<<<dim3(HW / 64, COUT / 64), 256>>>(wh, wlp, y0h, y0l, t1, CIN, s0, q0);
    dw_kernel<<<dim3(HW / 4 / 256, COUT), 256>>>(t1, dw1, t2h, t2l, s0, q0, g_r, b_r);

    gemm_kernel<<<dim3(HW / 64, COUT / 64), 256>>>(wh + W0, wlp + W0, t2h, t2l, t3, COUT, s1, q1);
    dw_kernel<<<dim3(HW / 4 / 256, COUT), 256>>>(t3, dw2, t2h, t2l, s1, q1, g1, b1);

    gemm_kernel<<<dim3(HW / 64, COUT / 64), 256>>>(wh + W0 + W1, wlp + W0 + W1, t2h, t2l, t1, COUT, s2, q2);
    apply_kernel<<<(COUT * HW / 4 + 255) / 256, 256>>>(t1, out, s2, q2, g2, b2);
}